// round 7
// baseline (speedup 1.0000x reference)
#include <cuda_runtime.h>
#include <cstdint>
#include <cstddef>

#define NTOK   32768
#define INDIM  512
#define DLAT   64
#define KCB    4096
#define NCBK   4
#define TILE_M 128
#define THREADS 128
#define NBLK   (NTOK / TILE_M)   // 256 CTAs
#define KT     64                // codewords per k-tile
#define NTILE  (KCB / KT)        // 64 tiles

typedef unsigned long long u64;

// Scratch (static device globals; rewritten every launch -> deterministic)
__device__ __align__(16) float g_esq[NCBK * KCB];
__device__ __align__(16) u64   g_ecbt[NCBK * 32 * KCB];   // [h][dp][k] f32x2-packed, 4MB

// ---- packed f32x2 + smem helpers ----
__device__ __forceinline__ u64 fma2(u64 a, u64 b, u64 c) {
    u64 d; asm("fma.rn.f32x2 %0, %1, %2, %3;" : "=l"(d) : "l"(a), "l"(b), "l"(c)); return d;
}
__device__ __forceinline__ u64 add2(u64 a, u64 b) {
    u64 d; asm("add.rn.f32x2 %0, %1, %2;" : "=l"(d) : "l"(a), "l"(b)); return d;
}
__device__ __forceinline__ u64 pk(float x, float y) {
    u64 d; asm("mov.b64 %0, {%1, %2};" : "=l"(d) : "f"(x), "f"(y)); return d;
}
__device__ __forceinline__ float2 upk(u64 v) {
    float2 r; asm("mov.b64 {%0, %1}, %2;" : "=f"(r.x), "=f"(r.y) : "l"(v)); return r;
}
__device__ __forceinline__ void lds_2x64(u64 &a, u64 &b, uint32_t addr) {
    asm volatile("ld.shared.v2.b64 {%0, %1}, [%2];" : "=l"(a), "=l"(b) : "r"(addr));
}
__device__ __forceinline__ u64 lds64(uint32_t a) { u64 v; asm volatile("ld.shared.b64 %0, [%1];" : "=l"(v) : "r"(a)); return v; }
__device__ __forceinline__ void sts64(uint32_t a, u64 v) { asm volatile("st.shared.b64 [%0], %1;" :: "r"(a), "l"(v)); }
__device__ __forceinline__ float lds32f(uint32_t a) { float v; asm volatile("ld.shared.f32 %0, [%1];" : "=f"(v) : "r"(a)); return v; }
__device__ __forceinline__ void sts32f(uint32_t a, float v) { asm volatile("st.shared.f32 [%0], %1;" :: "r"(a), "f"(v)); }
__device__ __forceinline__ int lds32i(uint32_t a) { int v; asm volatile("ld.shared.s32 %0, [%1];" : "=r"(v) : "r"(a)); return v; }
__device__ __forceinline__ void sts32i(uint32_t a, int v) { asm volatile("st.shared.s32 [%0], %1;" :: "r"(a), "r"(v)); }
__device__ __forceinline__ void cpa16(uint32_t dst, const void* src) {
    asm volatile("cp.async.cg.shared.global [%0], [%1], 16;" :: "r"(dst), "l"(src));
}
#define CP_COMMIT() asm volatile("cp.async.commit_group;")
#define CP_WAIT1()  asm volatile("cp.async.wait_group 1;")
#define CP_WAIT0()  asm volatile("cp.async.wait_group 0;")

// smem layout (bytes, dynamic)
#define R_S     0        // u64[32 dp][128 tok]                 32768
#define E_S     32768    // u64[2 buf][32 dp][64 k]             32768 (stage0 doubles as Wq/Wp tile)
#define ESQ_S   65536    // float[2 buf][64]                    512
#define REDD_S  66048    // float[128 tok][8 tk]                4096
#define REDI_S  70144    // int  [128 tok][8 tk]                4096
#define RN_S    74240    // float[128]                          512
#define SMEM_TOT 74752

// ---- prep: e_sq + transposed/packed codebook ----
__global__ void prep_kernel(const float* __restrict__ cb) {
    int idx = blockIdx.x * 128 + threadIdx.x;      // h*4096 + k
    if (idx < NCBK * KCB) {
        const float4* p = (const float4*)(cb + (size_t)idx * DLAT);
        int h = idx >> 12, k = idx & 4095;
        float s = 0.0f;
        #pragma unroll
        for (int q = 0; q < 16; q++) {
            float4 v = p[q];
            s = fmaf(v.x, v.x, s); s = fmaf(v.y, v.y, s);
            s = fmaf(v.z, v.z, s); s = fmaf(v.w, v.w, s);
            g_ecbt[(size_t)((h * 32 + 2 * q    ) << 12) + k] = pk(v.x, v.y);
            g_ecbt[(size_t)((h * 32 + 2 * q + 1) << 12) + k] = pk(v.z, v.w);
        }
        g_esq[idx] = s;
    }
}

// ---- fused: zl -> 4x(distance GEMM + argmin + residual) -> out ----
__global__ void __launch_bounds__(THREADS, 2)
fused_vq_kernel(const float* __restrict__ z,  const float* __restrict__ Wq,
                const float* __restrict__ bq, const float* __restrict__ cb,
                const float* __restrict__ Wp, const float* __restrict__ bp,
                float* __restrict__ out)
{
    extern __shared__ __align__(16) char smem[];
    const uint32_t sb = (uint32_t)__cvta_generic_to_shared(smem);

    const int t  = threadIdx.x;                 // == token-in-tile for phases 1/3
    const int tt = t >> 3;                      // 16 token groups (8 tokens each)
    const int tk = t & 7;                       // 8 k groups
    const int tok = blockIdx.x * TILE_M + t;
    const u64 NEG1 = pk(-1.0f, -1.0f);

    // ======================= Phase 1: zl = z @ Wq + bq (1 token/thread) ======
    u64 rr[32];
    {
        const float2* bq2 = (const float2*)bq;
        #pragma unroll
        for (int q = 0; q < 32; q++) { float2 v = bq2[q]; rr[q] = pk(v.x, v.y); }
    }
    const float4* zrow4 = (const float4*)(z + (size_t)tok * INDIM);
    for (int ic = 0; ic < 8; ic++) {
        __syncthreads();
        {   // Wq rows [ic*64, +64) -> e_s[0] region as [row][64]
            const float4* src = (const float4*)(Wq + (size_t)ic * 64 * DLAT);
            float4* dst = (float4*)(smem + E_S);
            #pragma unroll
            for (int i = 0; i < 8; i++) dst[t + i * THREADS] = src[t + i * THREADS];
        }
        __syncthreads();
        for (int i4 = 0; i4 < 16; i4++) {
            float4 zz = zrow4[ic * 16 + i4];
            float zs[4] = {zz.x, zz.y, zz.z, zz.w};
            #pragma unroll
            for (int j = 0; j < 4; j++) {
                u64 zd = pk(zs[j], zs[j]);
                uint32_t base = sb + E_S + (uint32_t)((i4 * 4 + j) * 256);
                #pragma unroll
                for (int q = 0; q < 16; q++) {
                    u64 a, b; lds_2x64(a, b, base + q * 16);
                    rr[2*q]   = fma2(a, zd, rr[2*q]);
                    rr[2*q+1] = fma2(b, zd, rr[2*q+1]);
                }
            }
        }
    }
    // write residual to smem transposed: r_s[dp][tok]
    #pragma unroll
    for (int p = 0; p < 32; p++) sts64(sb + R_S + (uint32_t)(p * 1024 + t * 8), rr[p]);

    // ======================= Phase 2: residual VQ, 4 codebooks ===============
    int bidxR[NCBK];

    for (int h = 0; h < NCBK; h++) {
        __syncthreads();   // r_s stable; e_s / red free

        // rnorm (own column; chain order == rel_err-0.0 lineage)
        {
            u64 rn2 = 0ULL;
            for (int p = 0; p < 32; p++) {
                u64 v = lds64(sb + R_S + (uint32_t)(p * 1024 + t * 8));
                rn2 = fma2(v, v, rn2);
            }
            float2 rv = upk(rn2);
            sts32f(sb + RN_S + (uint32_t)(t * 4), __fadd_rn(rv.x, rv.y));
        }

        const char* et  = (const char*)&g_ecbt[(size_t)h * 32 * KCB];  // [dp][k] u64
        const char* esq = (const char*)&g_esq[h * KCB];

        // prologue: tile 0 -> buf 0
        {
            uint32_t d0 = sb + E_S;
            #pragma unroll
            for (int i = 0; i < 8; i++) {
                int f4 = t + i * THREADS;         // 1024 f4 per tile
                int row = f4 >> 5, c16 = f4 & 31;
                cpa16(d0 + (uint32_t)(f4 * 16), et + (size_t)row * (KCB * 8) + c16 * 16);
            }
            if (t < 16) cpa16(sb + ESQ_S + (uint32_t)(t * 16), esq + t * 16);
            CP_COMMIT();
        }
        __syncthreads();   // rnorm_s visible
        float rn8[8];
        #pragma unroll
        for (int i = 0; i < 8; i++) rn8[i] = lds32f(sb + RN_S + (uint32_t)((tt * 8 + i) * 4));

        float best[8]; int bidx8[8];
        #pragma unroll
        for (int i = 0; i < 8; i++) { best[i] = 3.402823466e38f; bidx8[i] = 0; }

        for (int tile = 0; tile < NTILE; tile++) {
            __syncthreads();                      // (1) prior tile's buffer free
            if (tile + 1 < NTILE) {
                uint32_t s = (uint32_t)((tile + 1) & 1);
                uint32_t d0 = sb + E_S + s * 16384;
                const char* esrc = et + (size_t)(tile + 1) * (KT * 8);
                #pragma unroll
                for (int i = 0; i < 8; i++) {
                    int f4 = t + i * THREADS;
                    int row = f4 >> 5, c16 = f4 & 31;
                    cpa16(d0 + (uint32_t)(f4 * 16), esrc + (size_t)row * (KCB * 8) + c16 * 16);
                }
                if (t < 16) cpa16(sb + ESQ_S + s * 256 + (uint32_t)(t * 16),
                                  esq + (size_t)(tile + 1) * (KT * 4) + t * 16);
                CP_COMMIT();
                CP_WAIT1();
            } else {
                CP_WAIT0();
            }
            __syncthreads();                      // (2) tile data visible
            const uint32_t buf = (uint32_t)(tile & 1);

            u64 acc[64];
            #pragma unroll
            for (int c = 0; c < 64; c++) acc[c] = 0ULL;
            const uint32_t rbase = sb + R_S + (uint32_t)(tt * 64);
            const uint32_t ebase = sb + E_S + buf * 16384 + (uint32_t)(tk * 64);
            #pragma unroll 2
            for (int dp = 0; dp < 32; dp++) {
                u64 rf[8], ef[8];
                uint32_t ra = rbase + (uint32_t)(dp * 1024);
                lds_2x64(rf[0], rf[1], ra);      lds_2x64(rf[2], rf[3], ra + 16);
                lds_2x64(rf[4], rf[5], ra + 32); lds_2x64(rf[6], rf[7], ra + 48);
                uint32_t ea = ebase + (uint32_t)(dp * 512);
                lds_2x64(ef[0], ef[1], ea);      lds_2x64(ef[2], ef[3], ea + 16);
                lds_2x64(ef[4], ef[5], ea + 32); lds_2x64(ef[6], ef[7], ea + 48);
                #pragma unroll
                for (int i = 0; i < 8; i++)
                    #pragma unroll
                    for (int j = 0; j < 8; j++)
                        acc[i * 8 + j] = fma2(rf[i], ef[j], acc[i * 8 + j]);
            }
            // distances + local argmin (j ascending -> first-min within thread)
            #pragma unroll
            for (int j = 0; j < 8; j++) {
                float es = lds32f(sb + ESQ_S + buf * 256 + (uint32_t)((tk * 8 + j) * 4));
                int kg = tile * KT + tk * 8 + j;
                #pragma unroll
                for (int i = 0; i < 8; i++) {
                    float2 v = upk(acc[i * 8 + j]);
                    float dot = __fadd_rn(v.x, v.y);
                    float dv = __fsub_rn(__fadd_rn(rn8[i], es), __fmul_rn(2.0f, dot));
                    if (dv < best[i]) { best[i] = dv; bidx8[i] = kg; }
                }
            }
        }

        // cross-thread merge: lexicographic (d, k) min == global first-occurrence
        #pragma unroll
        for (int i = 0; i < 8; i++) {
            sts32f(sb + REDD_S + (uint32_t)(((tt * 8 + i) * 8 + tk) * 4), best[i]);
            sts32i(sb + REDI_S + (uint32_t)(((tt * 8 + i) * 8 + tk) * 4), bidx8[i]);
        }
        __syncthreads();
        {
            float bd = 3.402823466e38f; int bi = 0x7fffffff;
            for (int c = 0; c < 8; c++) {
                float d = lds32f(sb + REDD_S + (uint32_t)((t * 8 + c) * 4));
                int   id = lds32i(sb + REDI_S + (uint32_t)((t * 8 + c) * 4));
                if (d < bd || (d == bd && id < bi)) { bd = d; bi = id; }
            }
            bidxR[h] = bi;
        }
        // residual update: own column, r -= E[bidx] (exact fp32 sub)
        {
            const float4* e4 = (const float4*)(cb + ((size_t)h * KCB + bidxR[h]) * DLAT);
            #pragma unroll
            for (int q = 0; q < 16; q++) {
                float4 e = e4[q];
                uint32_t a0 = sb + R_S + (uint32_t)((2 * q) * 1024 + t * 8);
                uint32_t a1 = a0 + 1024;
                sts64(a0, fma2(pk(e.x, e.y), NEG1, lds64(a0)));
                sts64(a1, fma2(pk(e.z, e.w), NEG1, lds64(a1)));
            }
        }
    }

    // ======================= Phase 3: out = zq @ Wp + bp (1 token/thread) ====
    u64 zq[32];
    #pragma unroll
    for (int q = 0; q < 32; q++) zq[q] = 0ULL;
    #pragma unroll
    for (int h = 0; h < NCBK; h++) {
        const float4* e4 = (const float4*)(cb + ((size_t)h * KCB + bidxR[h]) * DLAT);
        #pragma unroll
        for (int q = 0; q < 16; q++) {
            float4 e = e4[q];
            zq[2*q]   = add2(zq[2*q],   pk(e.x, e.y));
            zq[2*q+1] = add2(zq[2*q+1], pk(e.z, e.w));
        }
    }

    float* orow = out + (size_t)tok * INDIM;
    for (int jc = 0; jc < 16; jc++) {
        __syncthreads();
        {   // Wp[:, jc*32 .. +32) -> e_s[0] region as [d][32]
            float4* dst = (float4*)(smem + E_S);
            #pragma unroll
            for (int i = 0; i < 4; i++) {
                int f4 = t + i * THREADS;          // 512 f4
                int d = f4 >> 3, jj4 = f4 & 7;
                dst[f4] = *(const float4*)(Wp + (size_t)d * INDIM + jc * 32 + jj4 * 4);
            }
        }
        __syncthreads();
        {
            u64 acc[16];
            const float2* bpp = (const float2*)(bp + jc * 32);
            #pragma unroll
            for (int q = 0; q < 16; q++) { float2 v = bpp[q]; acc[q] = pk(v.x, v.y); }
            #pragma unroll 4
            for (int dp = 0; dp < 32; dp++) {
                float2 zz = upk(zq[dp]);
                u64 z0p = pk(zz.x, zz.x), z1p = pk(zz.y, zz.y);
                uint32_t row0 = sb + E_S + (uint32_t)((2 * dp) * 128);
                #pragma unroll
                for (int q = 0; q < 8; q++) {
                    u64 a, b; lds_2x64(a, b, row0 + q * 16);
                    acc[2*q]   = fma2(a, z0p, acc[2*q]);
                    acc[2*q+1] = fma2(b, z0p, acc[2*q+1]);
                }
                uint32_t row1 = row0 + 128;
                #pragma unroll
                for (int q = 0; q < 8; q++) {
                    u64 a, b; lds_2x64(a, b, row1 + q * 16);
                    acc[2*q]   = fma2(a, z1p, acc[2*q]);
                    acc[2*q+1] = fma2(b, z1p, acc[2*q+1]);
                }
            }
            float4* od = (float4*)(orow + jc * 32);
            #pragma unroll
            for (int q8 = 0; q8 < 8; q8++) {
                float2 a = upk(acc[2*q8]), b = upk(acc[2*q8+1]);
                float4 v; v.x = a.x; v.y = a.y; v.z = b.x; v.w = b.y;
                od[q8] = v;
            }
        }
    }
}

extern "C" void kernel_launch(void* const* d_in, const int* in_sizes, int n_in,
                              void* d_out, int out_size)
{
    const float* z  = (const float*)d_in[0];
    const float* Wq = (const float*)d_in[1];
    const float* bq = (const float*)d_in[2];
    const float* cb = (const float*)d_in[3];
    const float* Wp = (const float*)d_in[4];
    const float* bp = (const float*)d_in[5];
    float* out = (float*)d_out;

    cudaFuncSetAttribute(fused_vq_kernel, cudaFuncAttributeMaxDynamicSharedMemorySize, SMEM_TOT);
    prep_kernel<<<(NCBK * KCB + 127) / 128, 128>>>(cb);
    fused_vq_kernel<<<NBLK, THREADS, SMEM_TOT>>>(z, Wq, bq, cb, Wp, bp, out);
}

// round 8
// speedup vs baseline: 1.3323x; 1.3323x over previous
#include <cuda_runtime.h>
#include <cstdint>
#include <cstddef>

#define NTOK   32768
#define INDIM  512
#define DLAT   64
#define KCB    4096
#define NCBK   4
#define TILE_M 128
#define THREADS 128
#define NBLK   (NTOK / TILE_M)   // 256 CTAs
#define KT     64                // codewords per k-tile
#define NTILE  (KCB / KT)        // 64 tiles

typedef unsigned long long u64;

// Scratch (static device globals; rewritten every launch -> deterministic)
__device__ __align__(16) float g_esq[NCBK * KCB];
__device__ __align__(16) u64   g_ecbt[NCBK * 32 * KCB];   // [h][dp][k] f32x2-packed, 4MB

// ---- packed f32x2 + smem helpers ----
__device__ __forceinline__ u64 fma2(u64 a, u64 b, u64 c) {
    u64 d; asm("fma.rn.f32x2 %0, %1, %2, %3;" : "=l"(d) : "l"(a), "l"(b), "l"(c)); return d;
}
__device__ __forceinline__ u64 add2(u64 a, u64 b) {
    u64 d; asm("add.rn.f32x2 %0, %1, %2;" : "=l"(d) : "l"(a), "l"(b)); return d;
}
__device__ __forceinline__ u64 pk(float x, float y) {
    u64 d; asm("mov.b64 %0, {%1, %2};" : "=l"(d) : "f"(x), "f"(y)); return d;
}
__device__ __forceinline__ float2 upk(u64 v) {
    float2 r; asm("mov.b64 {%0, %1}, %2;" : "=f"(r.x), "=f"(r.y) : "l"(v)); return r;
}
__device__ __forceinline__ void lds_2x64(u64 &a, u64 &b, uint32_t addr) {
    asm volatile("ld.shared.v2.b64 {%0, %1}, [%2];" : "=l"(a), "=l"(b) : "r"(addr));
}
__device__ __forceinline__ u64 lds64(uint32_t a) { u64 v; asm volatile("ld.shared.b64 %0, [%1];" : "=l"(v) : "r"(a)); return v; }
__device__ __forceinline__ void sts64(uint32_t a, u64 v) { asm volatile("st.shared.b64 [%0], %1;" :: "r"(a), "l"(v)); }
__device__ __forceinline__ float lds32f(uint32_t a) { float v; asm volatile("ld.shared.f32 %0, [%1];" : "=f"(v) : "r"(a)); return v; }
__device__ __forceinline__ void sts32f(uint32_t a, float v) { asm volatile("st.shared.f32 [%0], %1;" :: "r"(a), "f"(v)); }
__device__ __forceinline__ int lds32i(uint32_t a) { int v; asm volatile("ld.shared.s32 %0, [%1];" : "=r"(v) : "r"(a)); return v; }
__device__ __forceinline__ void sts32i(uint32_t a, int v) { asm volatile("st.shared.s32 [%0], %1;" :: "r"(a), "r"(v)); }
__device__ __forceinline__ void cpa16(uint32_t dst, const void* src) {
    asm volatile("cp.async.cg.shared.global [%0], [%1], 16;" :: "r"(dst), "l"(src));
}
#define CP_COMMIT() asm volatile("cp.async.commit_group;")
#define CP_WAIT1()  asm volatile("cp.async.wait_group 1;")
#define CP_WAIT0()  asm volatile("cp.async.wait_group 0;")

// smem layout (bytes, dynamic)
#define R_S     0        // u64 tile: (dp,tok) at dp*1024 + ((i>>1)&3)*256 + g*16 + (i&1)*8   32768
#define E_S     32768    // u64 tile x2 buf: (dp,kk) at dp*512 + ((kk>>1)&3)*128 + (kk>>3)*16 + (kk&1)*8   32768
#define ESQ_S   65536    // float[2 buf][64]                    512
#define REDD_S  66048    // float[128 tok][8 tk]                4096
#define REDI_S  70144    // int  [128 tok][8 tk]                4096
#define RN_S    74240    // float[128]                          512
#define SMEM_TOT 74752

// ---- prep: e_sq + transposed/packed codebook ----
__global__ void prep_kernel(const float* __restrict__ cb) {
    int idx = blockIdx.x * 128 + threadIdx.x;      // h*4096 + k
    if (idx < NCBK * KCB) {
        const float4* p = (const float4*)(cb + (size_t)idx * DLAT);
        int h = idx >> 12, k = idx & 4095;
        float s = 0.0f;
        #pragma unroll
        for (int q = 0; q < 16; q++) {
            float4 v = p[q];
            s = fmaf(v.x, v.x, s); s = fmaf(v.y, v.y, s);
            s = fmaf(v.z, v.z, s); s = fmaf(v.w, v.w, s);
            g_ecbt[(size_t)((h * 32 + 2 * q    ) << 12) + k] = pk(v.x, v.y);
            g_ecbt[(size_t)((h * 32 + 2 * q + 1) << 12) + k] = pk(v.z, v.w);
        }
        g_esq[idx] = s;
    }
}

// ---- fused: zl -> 4x(distance GEMM + argmin + residual) -> out ----
__global__ void __launch_bounds__(THREADS, 2)
fused_vq_kernel(const float* __restrict__ z,  const float* __restrict__ Wq,
                const float* __restrict__ bq, const float* __restrict__ cb,
                const float* __restrict__ Wp, const float* __restrict__ bp,
                float* __restrict__ out)
{
    extern __shared__ __align__(16) char smem[];
    const uint32_t sb = (uint32_t)__cvta_generic_to_shared(smem);

    const int t  = threadIdx.x;                 // == token-in-tile for phases 1/3
    const int tt = t >> 3;                      // 16 token groups (8 tokens each)
    const int tk = t & 7;                       // 8 k groups
    const int tok = blockIdx.x * TILE_M + t;
    const u64 NEG1 = pk(-1.0f, -1.0f);
    // own-token column offset in swizzled R tile: g=t>>3, i=t&7
    const uint32_t coff = (uint32_t)((((t >> 1) & 3) * 256) + ((t >> 3) * 16) + ((t & 1) * 8));

    // ======================= Phase 1: zl = z @ Wq + bq (1 token/thread) ======
    u64 rr[32];
    {
        const float2* bq2 = (const float2*)bq;
        #pragma unroll
        for (int q = 0; q < 32; q++) { float2 v = bq2[q]; rr[q] = pk(v.x, v.y); }
    }
    const float4* zrow4 = (const float4*)(z + (size_t)tok * INDIM);
    for (int ic = 0; ic < 8; ic++) {
        __syncthreads();
        {   // Wq rows [ic*64, +64) -> e_s[0] region as [row][64]
            const float4* src = (const float4*)(Wq + (size_t)ic * 64 * DLAT);
            float4* dst = (float4*)(smem + E_S);
            #pragma unroll
            for (int i = 0; i < 8; i++) dst[t + i * THREADS] = src[t + i * THREADS];
        }
        __syncthreads();
        for (int i4 = 0; i4 < 16; i4++) {
            float4 zz = zrow4[ic * 16 + i4];
            float zs[4] = {zz.x, zz.y, zz.z, zz.w};
            #pragma unroll
            for (int j = 0; j < 4; j++) {
                u64 zd = pk(zs[j], zs[j]);
                uint32_t base = sb + E_S + (uint32_t)((i4 * 4 + j) * 256);
                #pragma unroll
                for (int q = 0; q < 16; q++) {
                    u64 a, b; lds_2x64(a, b, base + q * 16);
                    rr[2*q]   = fma2(a, zd, rr[2*q]);
                    rr[2*q+1] = fma2(b, zd, rr[2*q+1]);
                }
            }
        }
    }
    // write residual to swizzled R tile
    #pragma unroll
    for (int p = 0; p < 32; p++) sts64(sb + R_S + (uint32_t)(p * 1024) + coff, rr[p]);

    // ======================= Phase 2: residual VQ, 4 codebooks ===============
    int bidxR[NCBK];

    for (int h = 0; h < NCBK; h++) {
        __syncthreads();   // r_s stable; e_s / red free

        // rnorm (own column; chain order == rel_err-0.0 lineage)
        {
            u64 rn2 = 0ULL;
            for (int p = 0; p < 32; p++) {
                u64 v = lds64(sb + R_S + (uint32_t)(p * 1024) + coff);
                rn2 = fma2(v, v, rn2);
            }
            float2 rv = upk(rn2);
            sts32f(sb + RN_S + (uint32_t)(t * 4), __fadd_rn(rv.x, rv.y));
        }

        const char* et  = (const char*)&g_ecbt[(size_t)h * 32 * KCB];  // [dp][k] u64
        const char* esq = (const char*)&g_esq[h * KCB];

        // prologue: tile 0 -> buf 0 (swizzled dest: pair p of 2 codewords)
        {
            uint32_t d0 = sb + E_S;
            #pragma unroll
            for (int i = 0; i < 8; i++) {
                int f4 = t + i * THREADS;         // 1024 f4 per tile
                int dp = f4 >> 5, p = f4 & 31;
                uint32_t doff = (uint32_t)(dp * 512 + (p & 3) * 128 + (p >> 2) * 16);
                cpa16(d0 + doff, et + (size_t)dp * (KCB * 8) + p * 16);
            }
            if (t < 16) cpa16(sb + ESQ_S + (uint32_t)(t * 16), esq + t * 16);
            CP_COMMIT();
        }
        __syncthreads();   // rnorm_s visible
        float rn8[8];
        #pragma unroll
        for (int i = 0; i < 8; i++) rn8[i] = lds32f(sb + RN_S + (uint32_t)((tt * 8 + i) * 4));

        float best[8]; int bidx8[8];
        #pragma unroll
        for (int i = 0; i < 8; i++) { best[i] = 3.402823466e38f; bidx8[i] = 0; }

        for (int tile = 0; tile < NTILE; tile++) {
            __syncthreads();                      // (1) prior tile's buffer free
            if (tile + 1 < NTILE) {
                uint32_t s = (uint32_t)((tile + 1) & 1);
                uint32_t d0 = sb + E_S + s * 16384;
                const char* esrc = et + (size_t)(tile + 1) * (KT * 8);
                #pragma unroll
                for (int i = 0; i < 8; i++) {
                    int f4 = t + i * THREADS;
                    int dp = f4 >> 5, p = f4 & 31;
                    uint32_t doff = (uint32_t)(dp * 512 + (p & 3) * 128 + (p >> 2) * 16);
                    cpa16(d0 + doff, esrc + (size_t)dp * (KCB * 8) + p * 16);
                }
                if (t < 16) cpa16(sb + ESQ_S + s * 256 + (uint32_t)(t * 16),
                                  esq + (size_t)(tile + 1) * (KT * 4) + t * 16);
                CP_COMMIT();
                CP_WAIT1();
            } else {
                CP_WAIT0();
            }
            __syncthreads();                      // (2) tile data visible
            const uint32_t buf = (uint32_t)(tile & 1);

            u64 acc[64];
            #pragma unroll
            for (int c = 0; c < 64; c++) acc[c] = 0ULL;
            const uint32_t rbase = sb + R_S + (uint32_t)(tt * 16);
            const uint32_t ebase = sb + E_S + buf * 16384 + (uint32_t)(tk * 16);
            #pragma unroll 2
            for (int dp = 0; dp < 32; dp++) {
                u64 rf[8], ef[8];
                uint32_t ra = rbase + (uint32_t)(dp * 1024);   // stride 256: conflict-free lanes
                lds_2x64(rf[0], rf[1], ra);       lds_2x64(rf[2], rf[3], ra + 256);
                lds_2x64(rf[4], rf[5], ra + 512); lds_2x64(rf[6], rf[7], ra + 768);
                uint32_t ea = ebase + (uint32_t)(dp * 512);    // stride 128: conflict-free lanes
                lds_2x64(ef[0], ef[1], ea);       lds_2x64(ef[2], ef[3], ea + 128);
                lds_2x64(ef[4], ef[5], ea + 256); lds_2x64(ef[6], ef[7], ea + 384);
                #pragma unroll
                for (int i = 0; i < 8; i++)
                    #pragma unroll
                    for (int j = 0; j < 8; j++)
                        acc[i * 8 + j] = fma2(rf[i], ef[j], acc[i * 8 + j]);
            }
            // distances + local argmin (j ascending -> first-min within thread)
            #pragma unroll
            for (int j = 0; j < 8; j++) {
                float es = lds32f(sb + ESQ_S + buf * 256 + (uint32_t)((tk * 8 + j) * 4));
                int kg = tile * KT + tk * 8 + j;
                #pragma unroll
                for (int i = 0; i < 8; i++) {
                    float2 v = upk(acc[i * 8 + j]);
                    float dot = __fadd_rn(v.x, v.y);
                    float dv = __fsub_rn(__fadd_rn(rn8[i], es), __fmul_rn(2.0f, dot));
                    if (dv < best[i]) { best[i] = dv; bidx8[i] = kg; }
                }
            }
        }

        // cross-thread merge: lexicographic (d, k) min == global first-occurrence
        #pragma unroll
        for (int i = 0; i < 8; i++) {
            sts32f(sb + REDD_S + (uint32_t)(((tt * 8 + i) * 8 + tk) * 4), best[i]);
            sts32i(sb + REDI_S + (uint32_t)(((tt * 8 + i) * 8 + tk) * 4), bidx8[i]);
        }
        __syncthreads();
        {
            float bd = 3.402823466e38f; int bi = 0x7fffffff;
            for (int c = 0; c < 8; c++) {
                float d = lds32f(sb + REDD_S + (uint32_t)((t * 8 + c) * 4));
                int   id = lds32i(sb + REDI_S + (uint32_t)((t * 8 + c) * 4));
                if (d < bd || (d == bd && id < bi)) { bd = d; bi = id; }
            }
            bidxR[h] = bi;
        }
        // residual update: own column, r -= E[bidx] (exact fp32 sub)
        {
            const float4* e4 = (const float4*)(cb + ((size_t)h * KCB + bidxR[h]) * DLAT);
            #pragma unroll
            for (int q = 0; q < 16; q++) {
                float4 e = e4[q];
                uint32_t a0 = sb + R_S + (uint32_t)((2 * q) * 1024) + coff;
                uint32_t a1 = a0 + 1024;
                sts64(a0, fma2(pk(e.x, e.y), NEG1, lds64(a0)));
                sts64(a1, fma2(pk(e.z, e.w), NEG1, lds64(a1)));
            }
        }
    }

    // ======================= Phase 3: out = zq @ Wp + bp (1 token/thread) ====
    u64 zq[32];
    #pragma unroll
    for (int q = 0; q < 32; q++) zq[q] = 0ULL;
    #pragma unroll
    for (int h = 0; h < NCBK; h++) {
        const float4* e4 = (const float4*)(cb + ((size_t)h * KCB + bidxR[h]) * DLAT);
        #pragma unroll
        for (int q = 0; q < 16; q++) {
            float4 e = e4[q];
            zq[2*q]   = add2(zq[2*q],   pk(e.x, e.y));
            zq[2*q+1] = add2(zq[2*q+1], pk(e.z, e.w));
        }
    }

    float* orow = out + (size_t)tok * INDIM;
    for (int jc = 0; jc < 16; jc++) {
        __syncthreads();
        {   // Wp[:, jc*32 .. +32) -> e_s[0] region as [d][32]
            float4* dst = (float4*)(smem + E_S);
            #pragma unroll
            for (int i = 0; i < 4; i++) {
                int f4 = t + i * THREADS;          // 512 f4
                int d = f4 >> 3, jj4 = f4 & 7;
                dst[f4] = *(const float4*)(Wp + (size_t)d * INDIM + jc * 32 + jj4 * 4);
            }
        }
        __syncthreads();
        {
            u64 acc[16];
            const float2* bpp = (const float2*)(bp + jc * 32);
            #pragma unroll
            for (int q = 0; q < 16; q++) { float2 v = bpp[q]; acc[q] = pk(v.x, v.y); }
            #pragma unroll 4
            for (int dp = 0; dp < 32; dp++) {
                float2 zz = upk(zq[dp]);
                u64 z0p = pk(zz.x, zz.x), z1p = pk(zz.y, zz.y);
                uint32_t row0 = sb + E_S + (uint32_t)((2 * dp) * 128);
                #pragma unroll
                for (int q = 0; q < 8; q++) {
                    u64 a, b; lds_2x64(a, b, row0 + q * 16);
                    acc[2*q]   = fma2(a, z0p, acc[2*q]);
                    acc[2*q+1] = fma2(b, z0p, acc[2*q+1]);
                }
                uint32_t row1 = row0 + 128;
                #pragma unroll
                for (int q = 0; q < 8; q++) {
                    u64 a, b; lds_2x64(a, b, row1 + q * 16);
                    acc[2*q]   = fma2(a, z1p, acc[2*q]);
                    acc[2*q+1] = fma2(b, z1p, acc[2*q+1]);
                }
            }
            float4* od = (float4*)(orow + jc * 32);
            #pragma unroll
            for (int q8 = 0; q8 < 8; q8++) {
                float2 a = upk(acc[2*q8]), b = upk(acc[2*q8+1]);
                float4 v; v.x = a.x; v.y = a.y; v.z = b.x; v.w = b.y;
                od[q8] = v;
            }
        }
    }
}

extern "C" void kernel_launch(void* const* d_in, const int* in_sizes, int n_in,
                              void* d_out, int out_size)
{
    const float* z  = (const float*)d_in[0];
    const float* Wq = (const float*)d_in[1];
    const float* bq = (const float*)d_in[2];
    const float* cb = (const float*)d_in[3];
    const float* Wp = (const float*)d_in[4];
    const float* bp = (const float*)d_in[5];
    float* out = (float*)d_out;

    cudaFuncSetAttribute(fused_vq_kernel, cudaFuncAttributeMaxDynamicSharedMemorySize, SMEM_TOT);
    prep_kernel<<<(NCBK * KCB + 127) / 128, 128>>>(cb);
    fused_vq_kernel<<<NBLK, THREADS, SMEM_TOT>>>(z, Wq, bq, cb, Wp, bp, out);
}

// round 9
// speedup vs baseline: 1.4594x; 1.0954x over previous
#include <cuda_runtime.h>
#include <cstdint>
#include <cstddef>

#define NTOK   32768
#define INDIM  512
#define DLAT   64
#define KCB    4096
#define NCBK   4
#define TILE_M 128
#define THREADS 128
#define NBLK   (NTOK / TILE_M)   // 256 CTAs
#define KR     128               // codewords per pipeline round (2 sub-tiles of 64)
#define NROUND (KCB / KR)        // 32 rounds

typedef unsigned long long u64;

// Scratch (static device globals; rewritten every launch -> deterministic)
__device__ __align__(16) float g_esq[NCBK * KCB];
__device__ __align__(16) u64   g_ecbt[NCBK * 32 * KCB];   // [h][dp][k] f32x2-packed, 4MB

// ---- packed f32x2 + smem helpers ----
__device__ __forceinline__ u64 fma2(u64 a, u64 b, u64 c) {
    u64 d; asm("fma.rn.f32x2 %0, %1, %2, %3;" : "=l"(d) : "l"(a), "l"(b), "l"(c)); return d;
}
__device__ __forceinline__ u64 add2(u64 a, u64 b) {
    u64 d; asm("add.rn.f32x2 %0, %1, %2;" : "=l"(d) : "l"(a), "l"(b)); return d;
}
__device__ __forceinline__ u64 pk(float x, float y) {
    u64 d; asm("mov.b64 %0, {%1, %2};" : "=l"(d) : "f"(x), "f"(y)); return d;
}
__device__ __forceinline__ float2 upk(u64 v) {
    float2 r; asm("mov.b64 {%0, %1}, %2;" : "=f"(r.x), "=f"(r.y) : "l"(v)); return r;
}
__device__ __forceinline__ void lds_2x64(u64 &a, u64 &b, uint32_t addr) {
    asm volatile("ld.shared.v2.b64 {%0, %1}, [%2];" : "=l"(a), "=l"(b) : "r"(addr));
}
// immediate-offset variant: zero address ALU in the hot loop
template<int IMM>
__device__ __forceinline__ void lds2i(u64 &a, u64 &b, uint32_t addr) {
    asm volatile("ld.shared.v2.b64 {%0, %1}, [%2+%3];" : "=l"(a), "=l"(b) : "r"(addr), "n"(IMM));
}
__device__ __forceinline__ u64 lds64(uint32_t a) { u64 v; asm volatile("ld.shared.b64 %0, [%1];" : "=l"(v) : "r"(a)); return v; }
__device__ __forceinline__ void sts64(uint32_t a, u64 v) { asm volatile("st.shared.b64 [%0], %1;" :: "r"(a), "l"(v)); }
__device__ __forceinline__ float lds32f(uint32_t a) { float v; asm volatile("ld.shared.f32 %0, [%1];" : "=f"(v) : "r"(a)); return v; }
__device__ __forceinline__ void sts32f(uint32_t a, float v) { asm volatile("st.shared.f32 [%0], %1;" :: "r"(a), "f"(v)); }
__device__ __forceinline__ int lds32i(uint32_t a) { int v; asm volatile("ld.shared.s32 %0, [%1];" : "=r"(v) : "r"(a)); return v; }
__device__ __forceinline__ void sts32i(uint32_t a, int v) { asm volatile("st.shared.s32 [%0], %1;" :: "r"(a), "r"(v)); }
__device__ __forceinline__ void cpa16(uint32_t dst, const void* src) {
    asm volatile("cp.async.cg.shared.global [%0], [%1], 16;" :: "r"(dst), "l"(src));
}
#define CP_COMMIT() asm volatile("cp.async.commit_group;")
#define CP_WAIT0()  asm volatile("cp.async.wait_group 0;")

// smem layout (bytes, dynamic)
#define R_S     0        // u64 tile: (dp,tok) at dp*1024 + ((i>>1)&3)*256 + g*16 + (i&1)*8   32768
#define E_S     32768    // 2 stages x 2 sub x swizzled 64-k tile (16KB each)                 65536
#define ESQ_S   98304    // float[2 stage][2 sub][64]                                          1024
#define REDD_S  99328    // float[128 tok][8 tk]                                               4096
#define REDI_S  103424   // int  [128 tok][8 tk]                                               4096
#define RN_S    107520   // float[128]                                                          512
#define SMEM_TOT 108032  // x2 CTAs = 216KB <= 228KB/SM

// ---- prep: e_sq + transposed/packed codebook ----
__global__ void prep_kernel(const float* __restrict__ cb) {
    int idx = blockIdx.x * 128 + threadIdx.x;      // h*4096 + k
    if (idx < NCBK * KCB) {
        const float4* p = (const float4*)(cb + (size_t)idx * DLAT);
        int h = idx >> 12, k = idx & 4095;
        float s = 0.0f;
        #pragma unroll
        for (int q = 0; q < 16; q++) {
            float4 v = p[q];
            s = fmaf(v.x, v.x, s); s = fmaf(v.y, v.y, s);
            s = fmaf(v.z, v.z, s); s = fmaf(v.w, v.w, s);
            g_ecbt[(size_t)((h * 32 + 2 * q    ) << 12) + k] = pk(v.x, v.y);
            g_ecbt[(size_t)((h * 32 + 2 * q + 1) << 12) + k] = pk(v.z, v.w);
        }
        g_esq[idx] = s;
    }
}

// one 8-dp block: 8 LDS.128 (immediate offsets) feeding 64 FFMA2
#define DP_BODY(D8)                                                            \
    {                                                                          \
        u64 rf[8], ef[8];                                                      \
        lds2i<(D8)*1024      >(rf[0], rf[1], ra);                              \
        lds2i<(D8)*1024 + 256>(rf[2], rf[3], ra);                              \
        lds2i<(D8)*1024 + 512>(rf[4], rf[5], ra);                              \
        lds2i<(D8)*1024 + 768>(rf[6], rf[7], ra);                              \
        lds2i<(D8)*512       >(ef[0], ef[1], ea);                              \
        lds2i<(D8)*512 + 128 >(ef[2], ef[3], ea);                              \
        lds2i<(D8)*512 + 256 >(ef[4], ef[5], ea);                              \
        lds2i<(D8)*512 + 384 >(ef[6], ef[7], ea);                              \
        _Pragma("unroll")                                                      \
        for (int i = 0; i < 8; i++)                                            \
            _Pragma("unroll")                                                  \
            for (int j = 0; j < 8; j++)                                        \
                acc[i * 8 + j] = fma2(rf[i], ef[j], acc[i * 8 + j]);           \
    }

// ---- fused: zl -> 4x(distance GEMM + argmin + residual) -> out ----
__global__ void __launch_bounds__(THREADS, 2)
fused_vq_kernel(const float* __restrict__ z,  const float* __restrict__ Wq,
                const float* __restrict__ bq, const float* __restrict__ cb,
                const float* __restrict__ Wp, const float* __restrict__ bp,
                float* __restrict__ out)
{
    extern __shared__ __align__(16) char smem[];
    const uint32_t sb = (uint32_t)__cvta_generic_to_shared(smem);

    const int t  = threadIdx.x;                 // == token-in-tile for phases 1/3
    const int tt = t >> 3;                      // 16 token groups (8 tokens each)
    const int tk = t & 7;                       // 8 k groups
    const int tok = blockIdx.x * TILE_M + t;
    const u64 NEG1 = pk(-1.0f, -1.0f);
    // own-token column offset in swizzled R tile
    const uint32_t coff = (uint32_t)((((t >> 1) & 3) * 256) + ((t >> 3) * 16) + ((t & 1) * 8));

    // ======================= Phase 1: zl = z @ Wq + bq (1 token/thread) ======
    u64 rr[32];
    {
        const float2* bq2 = (const float2*)bq;
        #pragma unroll
        for (int q = 0; q < 32; q++) { float2 v = bq2[q]; rr[q] = pk(v.x, v.y); }
    }
    const float4* zrow4 = (const float4*)(z + (size_t)tok * INDIM);
    for (int ic = 0; ic < 8; ic++) {
        __syncthreads();
        {   // Wq rows [ic*64, +64) -> E_S region as [row][64]
            const float4* src = (const float4*)(Wq + (size_t)ic * 64 * DLAT);
            float4* dst = (float4*)(smem + E_S);
            #pragma unroll
            for (int i = 0; i < 8; i++) dst[t + i * THREADS] = src[t + i * THREADS];
        }
        __syncthreads();
        for (int i4 = 0; i4 < 16; i4++) {
            float4 zz = zrow4[ic * 16 + i4];
            float zs[4] = {zz.x, zz.y, zz.z, zz.w};
            #pragma unroll
            for (int j = 0; j < 4; j++) {
                u64 zd = pk(zs[j], zs[j]);
                uint32_t base = sb + E_S + (uint32_t)((i4 * 4 + j) * 256);
                #pragma unroll
                for (int q = 0; q < 16; q++) {
                    u64 a, b; lds_2x64(a, b, base + q * 16);
                    rr[2*q]   = fma2(a, zd, rr[2*q]);
                    rr[2*q+1] = fma2(b, zd, rr[2*q+1]);
                }
            }
        }
    }
    // write residual to swizzled R tile
    #pragma unroll
    for (int p = 0; p < 32; p++) sts64(sb + R_S + (uint32_t)(p * 1024) + coff, rr[p]);

    // ======================= Phase 2: residual VQ, 4 codebooks ===============
    int bidxR[NCBK];

    for (int h = 0; h < NCBK; h++) {
        __syncthreads();   // r_s stable (prev update done); all E stages free

        // rnorm (own column; chain order == rel_err-0.0 lineage)
        {
            u64 rn2 = 0ULL;
            for (int p = 0; p < 32; p++) {
                u64 v = lds64(sb + R_S + (uint32_t)(p * 1024) + coff);
                rn2 = fma2(v, v, rn2);
            }
            float2 rv = upk(rn2);
            sts32f(sb + RN_S + (uint32_t)(t * 4), __fadd_rn(rv.x, rv.y));
        }
        __syncthreads();   // rnorm visible
        float rn8[8];
        #pragma unroll
        for (int i = 0; i < 8; i++) rn8[i] = lds32f(sb + RN_S + (uint32_t)((tt * 8 + i) * 4));

        const char* et  = (const char*)&g_ecbt[(size_t)h * 32 * KCB];  // [dp][k] u64
        const char* esq = (const char*)&g_esq[h * KCB];

        // prologue: round 0 -> stage 0 (32KB + esq)
        {
            uint32_t d0 = sb + E_S;
            #pragma unroll
            for (int i = 0; i < 16; i++) {
                int f4 = t + i * THREADS;          // 2048 f4 per round
                int u = f4 >> 10, rem = f4 & 1023;
                int dp = rem >> 5, p = rem & 31;
                uint32_t doff = (uint32_t)(u * 16384 + dp * 512 + (p & 3) * 128 + (p >> 2) * 16);
                cpa16(d0 + doff, et + (size_t)dp * (KCB * 8) + (size_t)(u * 64) * 8 + p * 16);
            }
            if (t < 32) cpa16(sb + ESQ_S + (uint32_t)(t * 16), esq + t * 16);
            CP_COMMIT();
        }

        float best[8]; int bidx8[8];
        #pragma unroll
        for (int i = 0; i < 8; i++) { best[i] = 3.402823466e38f; bidx8[i] = 0; }

        for (int round = 0; round < NROUND; round++) {
            CP_WAIT0();        // own copies for this round landed
            __syncthreads();   // everyone's copies visible; prev stage free
            if (round + 1 < NROUND) {
                uint32_t s = (uint32_t)((round + 1) & 1);
                uint32_t d0 = sb + E_S + s * 32768;
                const char* esrc = et + (size_t)((round + 1) * KR) * 8;
                #pragma unroll
                for (int i = 0; i < 16; i++) {
                    int f4 = t + i * THREADS;
                    int u = f4 >> 10, rem = f4 & 1023;
                    int dp = rem >> 5, p = rem & 31;
                    uint32_t doff = (uint32_t)(u * 16384 + dp * 512 + (p & 3) * 128 + (p >> 2) * 16);
                    cpa16(d0 + doff, esrc + (size_t)dp * (KCB * 8) + (size_t)(u * 64) * 8 + p * 16);
                }
                if (t < 32) cpa16(sb + ESQ_S + s * 512 + (uint32_t)(t * 16),
                                  esq + (size_t)((round + 1) * KR) * 4 + t * 16);
                CP_COMMIT();
            }
            const uint32_t stage = (uint32_t)(round & 1);

            #pragma unroll 1
            for (int u = 0; u < 2; u++) {
                u64 acc[64];
                #pragma unroll
                for (int c = 0; c < 64; c++) acc[c] = 0ULL;
                uint32_t ra = sb + R_S + (uint32_t)(tt * 16);
                uint32_t ea = sb + E_S + stage * 32768 + (uint32_t)(u * 16384 + tk * 16);
                #pragma unroll 1
                for (int ii = 0; ii < 4; ii++) {
                    DP_BODY(0) DP_BODY(1) DP_BODY(2) DP_BODY(3)
                    DP_BODY(4) DP_BODY(5) DP_BODY(6) DP_BODY(7)
                    ra += 8192; ea += 4096;
                }
                // distances + local argmin (j ascending -> first-min within thread)
                uint32_t esb = sb + ESQ_S + stage * 512 + (uint32_t)(u * 256 + tk * 32);
                int kg0 = round * KR + u * 64 + tk * 8;
                #pragma unroll
                for (int j = 0; j < 8; j++) {
                    float es = lds32f(esb + (uint32_t)(j * 4));
                    #pragma unroll
                    for (int i = 0; i < 8; i++) {
                        float2 v = upk(acc[i * 8 + j]);
                        float dot = __fadd_rn(v.x, v.y);
                        float dv = __fsub_rn(__fadd_rn(rn8[i], es), __fmul_rn(2.0f, dot));
                        if (dv < best[i]) { best[i] = dv; bidx8[i] = kg0 + j; }
                    }
                }
            }
        }

        // cross-thread merge: lexicographic (d, k) min == global first-occurrence
        #pragma unroll
        for (int i = 0; i < 8; i++) {
            sts32f(sb + REDD_S + (uint32_t)(((tt * 8 + i) * 8 + tk) * 4), best[i]);
            sts32i(sb + REDI_S + (uint32_t)(((tt * 8 + i) * 8 + tk) * 4), bidx8[i]);
        }
        __syncthreads();
        {
            float bd = 3.402823466e38f; int bi = 0x7fffffff;
            for (int c = 0; c < 8; c++) {
                float d = lds32f(sb + REDD_S + (uint32_t)((t * 8 + c) * 4));
                int   id = lds32i(sb + REDI_S + (uint32_t)((t * 8 + c) * 4));
                if (d < bd || (d == bd && id < bi)) { bd = d; bi = id; }
            }
            bidxR[h] = bi;
        }
        // residual update: own column, r -= E[bidx] (exact fp32 sub)
        {
            const float4* e4 = (const float4*)(cb + ((size_t)h * KCB + bidxR[h]) * DLAT);
            #pragma unroll
            for (int q = 0; q < 16; q++) {
                float4 e = e4[q];
                uint32_t a0 = sb + R_S + (uint32_t)((2 * q) * 1024) + coff;
                uint32_t a1 = a0 + 1024;
                sts64(a0, fma2(pk(e.x, e.y), NEG1, lds64(a0)));
                sts64(a1, fma2(pk(e.z, e.w), NEG1, lds64(a1)));
            }
        }
    }

    // ======================= Phase 3: out = zq @ Wp + bp (1 token/thread) ====
    u64 zq[32];
    #pragma unroll
    for (int q = 0; q < 32; q++) zq[q] = 0ULL;
    #pragma unroll
    for (int h = 0; h < NCBK; h++) {
        const float4* e4 = (const float4*)(cb + ((size_t)h * KCB + bidxR[h]) * DLAT);
        #pragma unroll
        for (int q = 0; q < 16; q++) {
            float4 e = e4[q];
            zq[2*q]   = add2(zq[2*q],   pk(e.x, e.y));
            zq[2*q+1] = add2(zq[2*q+1], pk(e.z, e.w));
        }
    }

    float* orow = out + (size_t)tok * INDIM;
    for (int jc = 0; jc < 16; jc++) {
        __syncthreads();
        {   // Wp[:, jc*32 .. +32) -> E_S region as [d][32]
            float4* dst = (float4*)(smem + E_S);
            #pragma unroll
            for (int i = 0; i < 4; i++) {
                int f4 = t + i * THREADS;          // 512 f4
                int d = f4 >> 3, jj4 = f4 & 7;
                dst[f4] = *(const float4*)(Wp + (size_t)d * INDIM + jc * 32 + jj4 * 4);
            }
        }
        __syncthreads();
        {
            u64 acc[16];
            const float2* bpp = (const float2*)(bp + jc * 32);
            #pragma unroll
            for (int q = 0; q < 16; q++) { float2 v = bpp[q]; acc[q] = pk(v.x, v.y); }
            #pragma unroll 4
            for (int dp = 0; dp < 32; dp++) {
                float2 zz = upk(zq[dp]);
                u64 z0p = pk(zz.x, zz.x), z1p = pk(zz.y, zz.y);
                uint32_t row0 = sb + E_S + (uint32_t)((2 * dp) * 128);
                #pragma unroll
                for (int q = 0; q < 8; q++) {
                    u64 a, b; lds_2x64(a, b, row0 + q * 16);
                    acc[2*q]   = fma2(a, z0p, acc[2*q]);
                    acc[2*q+1] = fma2(b, z0p, acc[2*q+1]);
                }
                uint32_t row1 = row0 + 128;
                #pragma unroll
                for (int q = 0; q < 8; q++) {
                    u64 a, b; lds_2x64(a, b, row1 + q * 16);
                    acc[2*q]   = fma2(a, z1p, acc[2*q]);
                    acc[2*q+1] = fma2(b, z1p, acc[2*q+1]);
                }
            }
            float4* od = (float4*)(orow + jc * 32);
            #pragma unroll
            for (int q8 = 0; q8 < 8; q8++) {
                float2 a = upk(acc[2*q8]), b = upk(acc[2*q8+1]);
                float4 v; v.x = a.x; v.y = a.y; v.z = b.x; v.w = b.y;
                od[q8] = v;
            }
        }
    }
}

extern "C" void kernel_launch(void* const* d_in, const int* in_sizes, int n_in,
                              void* d_out, int out_size)
{
    const float* z  = (const float*)d_in[0];
    const float* Wq = (const float*)d_in[1];
    const float* bq = (const float*)d_in[2];
    const float* cb = (const float*)d_in[3];
    const float* Wp = (const float*)d_in[4];
    const float* bp = (const float*)d_in[5];
    float* out = (float*)d_out;

    cudaFuncSetAttribute(fused_vq_kernel, cudaFuncAttributeMaxDynamicSharedMemorySize, SMEM_TOT);
    prep_kernel<<<(NCBK * KCB + 127) / 128, 128>>>(cb);
    fused_vq_kernel<<<NBLK, THREADS, SMEM_TOT>>>(z, Wq, bq, cb, Wp, bp, out);
}

// round 12
// speedup vs baseline: 2.0554x; 1.4084x over previous
#include <cuda_runtime.h>
#include <cuda_bf16.h>
#include <cstdint>
#include <cstddef>

#define NTOK   32768
#define INDIM  512
#define DLAT   64
#define KCB    4096
#define NCBK   4
#define TILE_M 128
#define THREADS 128
#define NBLK   (NTOK / TILE_M)   // 256 CTAs
#define NT2    32                // tiles of 128 codewords

typedef unsigned long long u64;

// Scratch (rewritten every launch -> deterministic)
__device__ __align__(16) float    g_esq[NCBK * KCB];
__device__ __align__(16) uint32_t g_ecbb[NCBK * KCB * 32];   // bf16x2 [h][k][dp], 2MB

// ---- packed f32x2 helpers ----
__device__ __forceinline__ u64 fma2(u64 a, u64 b, u64 c) {
    u64 d; asm("fma.rn.f32x2 %0, %1, %2, %3;" : "=l"(d) : "l"(a), "l"(b), "l"(c)); return d;
}
__device__ __forceinline__ u64 add2(u64 a, u64 b) {
    u64 d; asm("add.rn.f32x2 %0, %1, %2;" : "=l"(d) : "l"(a), "l"(b)); return d;
}
__device__ __forceinline__ u64 pk(float x, float y) {
    u64 d; asm("mov.b64 %0, {%1, %2};" : "=l"(d) : "f"(x), "f"(y)); return d;
}
__device__ __forceinline__ float2 upk(u64 v) {
    float2 r; asm("mov.b64 {%0, %1}, %2;" : "=f"(r.x), "=f"(r.y) : "l"(v)); return r;
}
__device__ __forceinline__ void lds_2x64(u64 &a, u64 &b, uint32_t addr) {
    asm volatile("ld.shared.v2.b64 {%0, %1}, [%2];" : "=l"(a), "=l"(b) : "r"(addr));
}
__device__ __forceinline__ float lds32f(uint32_t a) { float v; asm volatile("ld.shared.f32 %0, [%1];" : "=f"(v) : "r"(a)); return v; }
__device__ __forceinline__ void sts128(uint32_t a, uint32_t c0, uint32_t c1, uint32_t c2, uint32_t c3) {
    asm volatile("st.shared.v4.b32 [%0], {%1,%2,%3,%4};" :: "r"(a), "r"(c0), "r"(c1), "r"(c2), "r"(c3));
}
__device__ __forceinline__ void sts1f(uint32_t a, float x) {
    asm volatile("st.shared.f32 [%0], %1;" :: "r"(a), "f"(x));
}
__device__ __forceinline__ void cpa16(uint32_t dst, const void* src) {
    asm volatile("cp.async.cg.shared.global [%0], [%1], 16;" :: "r"(dst), "l"(src));
}
#define CP_COMMIT() asm volatile("cp.async.commit_group;")
#define CP_WAIT1()  asm volatile("cp.async.wait_group 1;")
#define CP_WAIT0()  asm volatile("cp.async.wait_group 0;")
#define SWZ(x) ((uint32_t)(x) ^ ((((uint32_t)(x)) >> 3) & 0x70))

// ---- warp-level tensor core (sm_80+ path; compiles for plain sm_100) ----
__device__ __forceinline__ void ldmx4(uint32_t* r, uint32_t addr) {
    asm volatile("ldmatrix.sync.aligned.m8n8.x4.shared.b16 {%0,%1,%2,%3}, [%4];"
                 : "=r"(r[0]), "=r"(r[1]), "=r"(r[2]), "=r"(r[3]) : "r"(addr));
}
__device__ __forceinline__ void ldmx2(uint32_t &r0, uint32_t &r1, uint32_t addr) {
    asm volatile("ldmatrix.sync.aligned.m8n8.x2.shared.b16 {%0,%1}, [%2];"
                 : "=r"(r0), "=r"(r1) : "r"(addr));
}
__device__ __forceinline__ void mma16816(float* d, const uint32_t* a, uint32_t b0, uint32_t b1) {
    asm volatile("mma.sync.aligned.m16n8k16.row.col.f32.bf16.bf16.f32 "
                 "{%0,%1,%2,%3}, {%4,%5,%6,%7}, {%8,%9}, {%0,%1,%2,%3};"
                 : "+f"(d[0]), "+f"(d[1]), "+f"(d[2]), "+f"(d[3])
                 : "r"(a[0]), "r"(a[1]), "r"(a[2]), "r"(a[3]), "r"(b0), "r"(b1));
}

// smem layout (bytes)
#define RB_S    0        // residual bf16 swizzled [128 tok][128B] = 16KB (A tile)
#define E_S     16384    // 2 slots x 16KB (B tiles; also Wq/Wp staging)
#define ESQ_S   49152    // 2 slots x 512B
#define D_S     50176    // 4 warps x [32 rows][33 f32] = 16896B (stride 33: scan conflict-free)
#define SMEM_TOT 67072   // x2 CTAs = 131KB

// ---- prep: e_sq (fp32, lineage order) + bf16-packed codebook ----
__global__ void prep_kernel(const float* __restrict__ cb) {
    int idx = blockIdx.x * 128 + threadIdx.x;   // h*4096 + k
    if (idx < NCBK * KCB) {
        const float4* p = (const float4*)(cb + (size_t)idx * DLAT);
        float s = 0.0f;
        #pragma unroll
        for (int q = 0; q < 16; q++) {
            float4 v = p[q];
            s = fmaf(v.x, v.x, s); s = fmaf(v.y, v.y, s);
            s = fmaf(v.z, v.z, s); s = fmaf(v.w, v.w, s);
            uint32_t b0, b1;
            asm("cvt.rn.bf16x2.f32 %0, %1, %2;" : "=r"(b0) : "f"(v.y), "f"(v.x));  // hi=y lo=x
            asm("cvt.rn.bf16x2.f32 %0, %1, %2;" : "=r"(b1) : "f"(v.w), "f"(v.z));
            g_ecbb[(size_t)idx * 32 + 2 * q]     = b0;
            g_ecbb[(size_t)idx * 32 + 2 * q + 1] = b1;
        }
        g_esq[idx] = s;
    }
}

// top-4 smallest insertion (sorted s0<=s1<=s2<=s3; ascending candidate order)
#define INS4(ds, cand) do {                                                    \
    if ((ds) < s3) {                                                           \
        if ((ds) < s2) { s3 = s2; i3 = i2;                                     \
            if ((ds) < s1) { s2 = s1; i2 = i1;                                 \
                if ((ds) < s0) { s1 = s0; i1 = i0; s0 = (ds); i0 = (cand); }   \
                else           { s1 = (ds); i1 = (cand); } }                   \
            else { s2 = (ds); i2 = (cand); } }                                 \
        else { s3 = (ds); i3 = (cand); } }                                     \
} while (0)

__global__ void __launch_bounds__(THREADS, 2)
fused_vq_kernel(const float* __restrict__ z,  const float* __restrict__ Wq,
                const float* __restrict__ bq, const float* __restrict__ cb,
                const float* __restrict__ Wp, const float* __restrict__ bp,
                float* __restrict__ out)
{
    extern __shared__ __align__(16) char smem[];
    const uint32_t sb = (uint32_t)__cvta_generic_to_shared(smem);

    const int t = threadIdx.x, wid = t >> 5, lane = t & 31;
    const int wbase = wid * 32;
    const int tok = blockIdx.x * TILE_M + t;      // thread owns token t end-to-end
    const u64 NEG1 = pk(-1.0f, -1.0f);

    // ============== Phase 1: zl = z @ Wq + bq (lineage; residual -> rr regs) ==============
    u64 rr[32];
    {
        const float2* bq2 = (const float2*)bq;
        #pragma unroll
        for (int q = 0; q < 32; q++) { float2 v = bq2[q]; rr[q] = pk(v.x, v.y); }
    }
    const float4* zrow4 = (const float4*)(z + (size_t)tok * INDIM);
    for (int ic = 0; ic < 8; ic++) {
        __syncthreads();
        {   // Wq rows [ic*64,+64) -> E_S as [row][64]
            const float4* src = (const float4*)(Wq + (size_t)ic * 64 * DLAT);
            float4* dst = (float4*)(smem + E_S);
            #pragma unroll
            for (int i = 0; i < 8; i++) dst[t + i * THREADS] = src[t + i * THREADS];
        }
        __syncthreads();
        for (int i4 = 0; i4 < 16; i4++) {
            float4 zz = zrow4[ic * 16 + i4];
            float zs[4] = {zz.x, zz.y, zz.z, zz.w};
            #pragma unroll
            for (int j = 0; j < 4; j++) {
                u64 zd = pk(zs[j], zs[j]);
                uint32_t base = sb + E_S + (uint32_t)((i4 * 4 + j) * 256);
                #pragma unroll
                for (int q = 0; q < 16; q++) {
                    u64 a, b; lds_2x64(a, b, base + q * 16);
                    rr[2*q]   = fma2(a, zd, rr[2*q]);
                    rr[2*q+1] = fma2(b, zd, rr[2*q+1]);
                }
            }
        }
    }

    // ============== Phase 2: per codebook: bf16 HMMA screen -> top4 -> exact rescore =====
    int bidx[NCBK];

    for (int h = 0; h < NCBK; h++) {
        __syncthreads();   // prior h fully done with E/D; RB free

        // write residual as bf16 into swizzled A tile (own row)
        #pragma unroll
        for (int u = 0; u < 8; u++) {
            uint32_t c[4];
            #pragma unroll
            for (int j = 0; j < 4; j++) {
                float2 v = upk(rr[u * 4 + j]);
                asm("cvt.rn.bf16x2.f32 %0, %1, %2;" : "=r"(c[j]) : "f"(v.y), "f"(v.x));
            }
            sts128(sb + RB_S + SWZ(t * 128 + u * 16), c[0], c[1], c[2], c[3]);
        }
        __syncwarp();      // A rows written by own warp's lanes only

        // rnorm (lineage chain)
        float rnorm;
        {
            u64 rn2 = 0ULL;
            #pragma unroll
            for (int q = 0; q < 32; q++) rn2 = fma2(rr[q], rr[q], rn2);
            float2 rv = upk(rn2);
            rnorm = __fadd_rn(rv.x, rv.y);
        }

        // A fragments: 2 m16 tiles x 4 ksteps, loaded once per codebook
        uint32_t af[2][4][4];
        {
            int arow = wbase + (lane & 15);
            uint32_t kb = (lane & 16) ? 16u : 0u;
            #pragma unroll
            for (int mt = 0; mt < 2; mt++)
                #pragma unroll
                for (int s = 0; s < 4; s++)
                    ldmx4(af[mt][s], sb + RB_S + SWZ((uint32_t)((arow + 16 * mt) * 128 + s * 32) + kb));
        }

        const char* eb  = (const char*)&g_ecbb[(size_t)h * KCB * 32];   // [k][128B]
        const char* esq = (const char*)&g_esq[h * KCB];

#define CP_E(tile, slot) do {                                                          \
        uint32_t _d0 = sb + E_S + (uint32_t)(slot) * 16384;                            \
        const char* _src = eb + (size_t)(tile) * 128 * 128;                            \
        _Pragma("unroll")                                                              \
        for (int i = 0; i < 8; i++) {                                                  \
            int f = t + i * THREADS; int row = f >> 3, u = f & 7;                      \
            cpa16(_d0 + SWZ(row * 128 + u * 16), _src + (size_t)row * 128 + u * 16);   \
        }                                                                              \
        if (t < 32) cpa16(sb + ESQ_S + (uint32_t)(slot) * 512 + t * 16,                \
                          esq + (size_t)(tile) * 512 + t * 16);                        \
    } while (0)

        CP_E(0, 0); CP_COMMIT();
        CP_E(1, 1); CP_COMMIT();
        CP_WAIT1();
        __syncthreads();   // E(0) visible everywhere

        float s0 = 3.4e38f, s1 = 3.4e38f, s2 = 3.4e38f, s3 = 3.4e38f;
        int   i0 = 0x7fffffff, i1 = 0x7fffffff, i2 = 0x7fffffff, i3 = 0x7fffffff;

        for (int tile = 0; tile < NT2; tile++) {
            const uint32_t ebase = sb + E_S + (uint32_t)((tile & 1) * 16384);
            const uint32_t esb   = sb + ESQ_S + (uint32_t)((tile & 1) * 512);
            const uint32_t dbase = sb + D_S + (uint32_t)(wid * 4224);
            #pragma unroll 1
            for (int chunk = 0; chunk < 4; chunk++) {
                #pragma unroll
                for (int nb = 0; nb < 4; nb++) {
                    float d0[4] = {0,0,0,0}, d1[4] = {0,0,0,0};
                    #pragma unroll
                    for (int s = 0; s < 4; s++) {
                        uint32_t b0, b1;
                        int brow = chunk * 32 + nb * 8 + (lane & 7);
                        ldmx2(b0, b1, ebase + SWZ((uint32_t)(brow * 128 + s * 32) + ((lane & 8) ? 16u : 0u)));
                        mma16816(d0, af[0][s], b0, b1);
                        mma16816(d1, af[1][s], b0, b1);
                    }
                    // D stores: scalar st.f32 (stride-33 rows are only 4B-aligned at odd rows)
                    int c0 = nb * 8 + (lane & 3) * 2;
                    int r0 = lane >> 2;
                    uint32_t a00 = dbase + (uint32_t)(((r0     ) * 33 + c0) * 4);
                    uint32_t a08 = dbase + (uint32_t)(((r0 +  8) * 33 + c0) * 4);
                    uint32_t a16 = dbase + (uint32_t)(((r0 + 16) * 33 + c0) * 4);
                    uint32_t a24 = dbase + (uint32_t)(((r0 + 24) * 33 + c0) * 4);
                    sts1f(a00, d0[0]); sts1f(a00 + 4, d0[1]);
                    sts1f(a08, d0[2]); sts1f(a08 + 4, d0[3]);
                    sts1f(a16, d1[0]); sts1f(a16 + 4, d1[1]);
                    sts1f(a24, d1[2]); sts1f(a24 + 4, d1[3]);
                }
                __syncwarp();
                // scan own token's row (stride-33 -> conflict-free; es broadcast)
                uint32_t drow = dbase + (uint32_t)(lane * 132);
                int kg0 = tile * 128 + chunk * 32;
                #pragma unroll 4
                for (int j = 0; j < 32; j++) {
                    float dot = lds32f(drow + (uint32_t)(j * 4));
                    float es  = lds32f(esb + (uint32_t)((chunk * 32 + j) * 4));
                    float ds  = fmaf(dot, -2.0f, es);
                    INS4(ds, kg0 + j);
                }
                __syncwarp();
            }
            __syncthreads();                       // all warps done reading slot tile&1
            if (tile + 2 < NT2) { CP_E(tile + 2, tile & 1); CP_COMMIT(); }
            if (tile + 1 < NT2) {
                if (tile + 2 < NT2) CP_WAIT1(); else CP_WAIT0();
                __syncthreads();                   // slot (tile+1)&1 visible
            }
        }
#undef CP_E

        // exact rescore of top-4 (lineage fp32 ordering; lexicographic (d, idx) = first-min)
        {
            float bd = 3.4e38f; int bi = 0x7fffffff;
            const float* cbh = cb + (size_t)h * KCB * DLAT;
            const float* esqf = g_esq + h * KCB;
#define RESCORE(ii) do {                                                       \
            int _c = (ii);                                                     \
            const float4* e4 = (const float4*)(cbh + (size_t)_c * DLAT);       \
            u64 aA = 0ULL, aB = 0ULL;                                          \
            _Pragma("unroll")                                                  \
            for (int q = 0; q < 16; q++) {                                     \
                float4 ev = e4[q];                                             \
                aA = fma2(pk(ev.x, ev.y), rr[2*q],   aA);                      \
                aB = fma2(pk(ev.z, ev.w), rr[2*q+1], aB);                      \
            }                                                                  \
            float2 va = upk(aA), vb = upk(aB);                                 \
            float dot = __fadd_rn(__fadd_rn(va.x, va.y), __fadd_rn(vb.x, vb.y)); \
            float dv = __fsub_rn(__fadd_rn(rnorm, esqf[_c]), __fmul_rn(2.0f, dot)); \
            if (dv < bd || (dv == bd && _c < bi)) { bd = dv; bi = _c; }        \
        } while (0)
            RESCORE(i0); RESCORE(i1); RESCORE(i2); RESCORE(i3);
#undef RESCORE
            bidx[h] = bi;
            // exact residual update (fp32 sub via fma2(e,-1,r))
            const float4* e4 = (const float4*)(cbh + (size_t)bi * DLAT);
            #pragma unroll
            for (int q = 0; q < 16; q++) {
                float4 ev = e4[q];
                rr[2*q]   = fma2(pk(ev.x, ev.y), NEG1, rr[2*q]);
                rr[2*q+1] = fma2(pk(ev.z, ev.w), NEG1, rr[2*q+1]);
            }
        }
    }

    // ============== Phase 3: out = zq @ Wp + bp (lineage) ==============
    u64 zq[32];
    #pragma unroll
    for (int q = 0; q < 32; q++) zq[q] = 0ULL;
    #pragma unroll
    for (int h = 0; h < NCBK; h++) {
        const float4* e4 = (const float4*)(cb + ((size_t)h * KCB + bidx[h]) * DLAT);
        #pragma unroll
        for (int q = 0; q < 16; q++) {
            float4 ev = e4[q];
            zq[2*q]   = add2(zq[2*q],   pk(ev.x, ev.y));
            zq[2*q+1] = add2(zq[2*q+1], pk(ev.z, ev.w));
        }
    }

    float* orow = out + (size_t)tok * INDIM;
    for (int jc = 0; jc < 16; jc++) {
        __syncthreads();
        {   // Wp[:, jc*32..+32) -> E_S as [d][32]
            float4* dst = (float4*)(smem + E_S);
            #pragma unroll
            for (int i = 0; i < 4; i++) {
                int f4 = t + i * THREADS;
                int d = f4 >> 3, jj4 = f4 & 7;
                dst[f4] = *(const float4*)(Wp + (size_t)d * INDIM + jc * 32 + jj4 * 4);
            }
        }
        __syncthreads();
        {
            u64 acc[16];
            const float2* bpp = (const float2*)(bp + jc * 32);
            #pragma unroll
            for (int q = 0; q < 16; q++) { float2 v = bpp[q]; acc[q] = pk(v.x, v.y); }
            #pragma unroll 4
            for (int dp = 0; dp < 32; dp++) {
                float2 zz = upk(zq[dp]);
                u64 z0p = pk(zz.x, zz.x), z1p = pk(zz.y, zz.y);
                uint32_t row0 = sb + E_S + (uint32_t)((2 * dp) * 128);
                #pragma unroll
                for (int q = 0; q < 8; q++) {
                    u64 a, b; lds_2x64(a, b, row0 + q * 16);
                    acc[2*q]   = fma2(a, z0p, acc[2*q]);
                    acc[2*q+1] = fma2(b, z0p, acc[2*q+1]);
                }
                uint32_t row1 = row0 + 128;
                #pragma unroll
                for (int q = 0; q < 8; q++) {
                    u64 a, b; lds_2x64(a, b, row1 + q * 16);
                    acc[2*q]   = fma2(a, z1p, acc[2*q]);
                    acc[2*q+1] = fma2(b, z1p, acc[2*q+1]);
                }
            }
            float4* od = (float4*)(orow + jc * 32);
            #pragma unroll
            for (int q8 = 0; q8 < 8; q8++) {
                float2 a = upk(acc[2*q8]), b = upk(acc[2*q8+1]);
                float4 v; v.x = a.x; v.y = a.y; v.z = b.x; v.w = b.y;
                od[q8] = v;
            }
        }
    }
}

extern "C" void kernel_launch(void* const* d_in, const int* in_sizes, int n_in,
                              void* d_out, int out_size)
{
    const float* z  = (const float*)d_in[0];
    const float* Wq = (const float*)d_in[1];
    const float* bq = (const float*)d_in[2];
    const float* cb = (const float*)d_in[3];
    const float* Wp = (const float*)d_in[4];
    const float* bp = (const float*)d_in[5];
    float* out = (float*)d_out;

    cudaFuncSetAttribute(fused_vq_kernel, cudaFuncAttributeMaxDynamicSharedMemorySize, SMEM_TOT);
    prep_kernel<<<(NCBK * KCB + 127) / 128, 128>>>(cb);
    fused_vq_kernel<<<NBLK, THREADS, SMEM_TOT>>>(z, Wq, bq, cb, Wp, bp, out);
}

// round 13
// speedup vs baseline: 2.8885x; 1.4053x over previous
#include <cuda_runtime.h>
#include <cuda_bf16.h>
#include <cstdint>
#include <cstddef>

#define NTOK   32768
#define INDIM  512
#define DLAT   64
#define KCB    4096
#define NCBK   4
#define TILE_M 128
#define THREADS 128
#define NBLK   (NTOK / TILE_M)   // 256 CTAs
#define NT2    32                // tiles of 128 codewords

typedef unsigned long long u64;

// Scratch (rewritten every launch -> deterministic)
__device__ __align__(16) float    g_esq[NCBK * KCB];
__device__ __align__(16) uint32_t g_ecbb[NCBK * KCB * 32];   // bf16x2 [h][k][dp], 2MB

// ---- packed f32x2 helpers ----
__device__ __forceinline__ u64 fma2(u64 a, u64 b, u64 c) {
    u64 d; asm("fma.rn.f32x2 %0, %1, %2, %3;" : "=l"(d) : "l"(a), "l"(b), "l"(c)); return d;
}
__device__ __forceinline__ u64 add2(u64 a, u64 b) {
    u64 d; asm("add.rn.f32x2 %0, %1, %2;" : "=l"(d) : "l"(a), "l"(b)); return d;
}
__device__ __forceinline__ u64 pk(float x, float y) {
    u64 d; asm("mov.b64 %0, {%1, %2};" : "=l"(d) : "f"(x), "f"(y)); return d;
}
__device__ __forceinline__ float2 upk(u64 v) {
    float2 r; asm("mov.b64 {%0, %1}, %2;" : "=f"(r.x), "=f"(r.y) : "l"(v)); return r;
}
__device__ __forceinline__ void lds_2x64(u64 &a, u64 &b, uint32_t addr) {
    asm volatile("ld.shared.v2.b64 {%0, %1}, [%2];" : "=l"(a), "=l"(b) : "r"(addr));
}
__device__ __forceinline__ float lds32f(uint32_t a) { float v; asm volatile("ld.shared.f32 %0, [%1];" : "=f"(v) : "r"(a)); return v; }
__device__ __forceinline__ int lds32i(uint32_t a) { int v; asm volatile("ld.shared.s32 %0, [%1];" : "=r"(v) : "r"(a)); return v; }
__device__ __forceinline__ float2 lds64f2(uint32_t a) {
    float2 v; asm volatile("ld.shared.v2.f32 {%0,%1}, [%2];" : "=f"(v.x), "=f"(v.y) : "r"(a)); return v;
}
__device__ __forceinline__ void sts128(uint32_t a, uint32_t c0, uint32_t c1, uint32_t c2, uint32_t c3) {
    asm volatile("st.shared.v4.b32 [%0], {%1,%2,%3,%4};" :: "r"(a), "r"(c0), "r"(c1), "r"(c2), "r"(c3));
}
__device__ __forceinline__ void sts1f(uint32_t a, float x) {
    asm volatile("st.shared.f32 [%0], %1;" :: "r"(a), "f"(x));
}
__device__ __forceinline__ void sts1i(uint32_t a, int x) {
    asm volatile("st.shared.s32 [%0], %1;" :: "r"(a), "r"(x));
}
__device__ __forceinline__ void cpa16(uint32_t dst, const void* src) {
    asm volatile("cp.async.cg.shared.global [%0], [%1], 16;" :: "r"(dst), "l"(src));
}
#define CP_COMMIT() asm volatile("cp.async.commit_group;")
#define CP_WAIT1()  asm volatile("cp.async.wait_group 1;")
#define CP_WAIT0()  asm volatile("cp.async.wait_group 0;")
#define SWZ(x) ((uint32_t)(x) ^ ((((uint32_t)(x)) >> 3) & 0x70))

// ---- warp-level tensor core (sm_80+ path) ----
__device__ __forceinline__ void ldmx4(uint32_t* r, uint32_t addr) {
    asm volatile("ldmatrix.sync.aligned.m8n8.x4.shared.b16 {%0,%1,%2,%3}, [%4];"
                 : "=r"(r[0]), "=r"(r[1]), "=r"(r[2]), "=r"(r[3]) : "r"(addr));
}
__device__ __forceinline__ void ldmx2(uint32_t &r0, uint32_t &r1, uint32_t addr) {
    asm volatile("ldmatrix.sync.aligned.m8n8.x2.shared.b16 {%0,%1}, [%2];"
                 : "=r"(r0), "=r"(r1) : "r"(addr));
}
__device__ __forceinline__ void mma16816(float* d, const uint32_t* a, uint32_t b0, uint32_t b1) {
    asm volatile("mma.sync.aligned.m16n8k16.row.col.f32.bf16.bf16.f32 "
                 "{%0,%1,%2,%3}, {%4,%5,%6,%7}, {%8,%9}, {%0,%1,%2,%3};"
                 : "+f"(d[0]), "+f"(d[1]), "+f"(d[2]), "+f"(d[3])
                 : "r"(a[0]), "r"(a[1]), "r"(a[2]), "r"(a[3]), "r"(b0), "r"(b1));
}

// smem layout (bytes)
#define RB_S    0        // residual bf16 swizzled [128 tok][128B] = 16KB (A tile)
#define E_S     16384    // 2 slots x 16KB (B tiles; also Wq/Wp staging)
#define ESQ_S   49152    // 2 slots x 512B
#define MG_S    50176    // merge: 4 warps x (dbuf f32[12][32] + ibuf s32[12][32]) = 12KB
#define SMEM_TOT 67072   // x2 CTAs = 131KB

// ---- prep: e_sq (fp32, lineage order) + bf16-packed codebook ----
__global__ void prep_kernel(const float* __restrict__ cb) {
    int idx = blockIdx.x * 128 + threadIdx.x;   // h*4096 + k
    if (idx < NCBK * KCB) {
        const float4* p = (const float4*)(cb + (size_t)idx * DLAT);
        float s = 0.0f;
        #pragma unroll
        for (int q = 0; q < 16; q++) {
            float4 v = p[q];
            s = fmaf(v.x, v.x, s); s = fmaf(v.y, v.y, s);
            s = fmaf(v.z, v.z, s); s = fmaf(v.w, v.w, s);
            uint32_t b0, b1;
            asm("cvt.rn.bf16x2.f32 %0, %1, %2;" : "=r"(b0) : "f"(v.y), "f"(v.x));  // hi=y lo=x
            asm("cvt.rn.bf16x2.f32 %0, %1, %2;" : "=r"(b1) : "f"(v.w), "f"(v.z));
            g_ecbb[(size_t)idx * 32 + 2 * q]     = b0;
            g_ecbb[(size_t)idx * 32 + 2 * q + 1] = b1;
        }
        g_esq[idx] = s;
    }
}

// top-3 smallest insertion per row-slot m (bd[m][0]<=bd[m][1]<=bd[m][2])
#define INS3(m, ds, cand) do {                                                 \
    float _v = (ds); int _c = (cand);                                          \
    if (_v < bd[m][2]) {                                                       \
        if (_v < bd[m][1]) {                                                   \
            bd[m][2] = bd[m][1]; bi[m][2] = bi[m][1];                          \
            if (_v < bd[m][0]) { bd[m][1] = bd[m][0]; bi[m][1] = bi[m][0];     \
                                 bd[m][0] = _v;       bi[m][0] = _c; }         \
            else               { bd[m][1] = _v;       bi[m][1] = _c; }         \
        } else { bd[m][2] = _v; bi[m][2] = _c; }                               \
    }                                                                          \
} while (0)

__global__ void __launch_bounds__(THREADS, 2)
fused_vq_kernel(const float* __restrict__ z,  const float* __restrict__ Wq,
                const float* __restrict__ bq, const float* __restrict__ cb,
                const float* __restrict__ Wp, const float* __restrict__ bp,
                float* __restrict__ out)
{
    extern __shared__ __align__(16) char smem[];
    const uint32_t sb = (uint32_t)__cvta_generic_to_shared(smem);

    const int t = threadIdx.x, wid = t >> 5, lane = t & 31;
    const int wbase = wid * 32;
    const int tok = blockIdx.x * TILE_M + t;      // thread owns token t end-to-end
    const u64 NEG1 = pk(-1.0f, -1.0f);

    // ============== Phase 1: zl = z @ Wq + bq (lineage; residual -> rr regs) ==============
    u64 rr[32];
    {
        const float2* bq2 = (const float2*)bq;
        #pragma unroll
        for (int q = 0; q < 32; q++) { float2 v = bq2[q]; rr[q] = pk(v.x, v.y); }
    }
    const float4* zrow4 = (const float4*)(z + (size_t)tok * INDIM);
    for (int ic = 0; ic < 8; ic++) {
        __syncthreads();
        {   // Wq rows [ic*64,+64) -> E_S as [row][64]
            const float4* src = (const float4*)(Wq + (size_t)ic * 64 * DLAT);
            float4* dst = (float4*)(smem + E_S);
            #pragma unroll
            for (int i = 0; i < 8; i++) dst[t + i * THREADS] = src[t + i * THREADS];
        }
        __syncthreads();
        for (int i4 = 0; i4 < 16; i4++) {
            float4 zz = zrow4[ic * 16 + i4];
            float zs[4] = {zz.x, zz.y, zz.z, zz.w};
            #pragma unroll
            for (int j = 0; j < 4; j++) {
                u64 zd = pk(zs[j], zs[j]);
                uint32_t base = sb + E_S + (uint32_t)((i4 * 4 + j) * 256);
                #pragma unroll
                for (int q = 0; q < 16; q++) {
                    u64 a, b; lds_2x64(a, b, base + q * 16);
                    rr[2*q]   = fma2(a, zd, rr[2*q]);
                    rr[2*q+1] = fma2(b, zd, rr[2*q+1]);
                }
            }
        }
    }

    // ============== Phase 2: bf16 HMMA screen (in-reg top-3/lane) -> exact rescore =====
    int bidx[NCBK];

    for (int h = 0; h < NCBK; h++) {
        __syncthreads();   // prior h fully done with E/merge; RB free

        // write residual as bf16 into swizzled A tile (own row)
        #pragma unroll
        for (int u = 0; u < 8; u++) {
            uint32_t c[4];
            #pragma unroll
            for (int j = 0; j < 4; j++) {
                float2 v = upk(rr[u * 4 + j]);
                asm("cvt.rn.bf16x2.f32 %0, %1, %2;" : "=r"(c[j]) : "f"(v.y), "f"(v.x));
            }
            sts128(sb + RB_S + SWZ(t * 128 + u * 16), c[0], c[1], c[2], c[3]);
        }
        __syncwarp();      // A rows written by own warp's lanes only

        // rnorm (lineage chain)
        float rnorm;
        {
            u64 rn2 = 0ULL;
            #pragma unroll
            for (int q = 0; q < 32; q++) rn2 = fma2(rr[q], rr[q], rn2);
            float2 rv = upk(rn2);
            rnorm = __fadd_rn(rv.x, rv.y);
        }

        // A fragments: 2 m16 tiles x 4 ksteps, loaded once per codebook
        uint32_t af[2][4][4];
        {
            int arow = wbase + (lane & 15);
            uint32_t kb = (lane & 16) ? 16u : 0u;
            #pragma unroll
            for (int mt = 0; mt < 2; mt++)
                #pragma unroll
                for (int s = 0; s < 4; s++)
                    ldmx4(af[mt][s], sb + RB_S + SWZ((uint32_t)((arow + 16 * mt) * 128 + s * 32) + kb));
        }

        const char* eb  = (const char*)&g_ecbb[(size_t)h * KCB * 32];   // [k][128B]
        const char* esq = (const char*)&g_esq[h * KCB];

#define CP_E(tile, slot) do {                                                          \
        uint32_t _d0 = sb + E_S + (uint32_t)(slot) * 16384;                            \
        const char* _src = eb + (size_t)(tile) * 128 * 128;                            \
        _Pragma("unroll")                                                              \
        for (int i = 0; i < 8; i++) {                                                  \
            int f = t + i * THREADS; int row = f >> 3, u = f & 7;                      \
            cpa16(_d0 + SWZ(row * 128 + u * 16), _src + (size_t)row * 128 + u * 16);   \
        }                                                                              \
        if (t < 32) cpa16(sb + ESQ_S + (uint32_t)(slot) * 512 + t * 16,                \
                          esq + (size_t)(tile) * 512 + t * 16);                        \
    } while (0)

        CP_E(0, 0); CP_COMMIT();
        CP_E(1, 1); CP_COMMIT();
        CP_WAIT1();
        __syncthreads();   // E(0) visible everywhere

        // per-lane top-3 for each of 4 owned row-slots: rows (lane>>2)+{0,8,16,24}
        float bd[4][3]; int bi[4][3];
        #pragma unroll
        for (int m = 0; m < 4; m++) {
            bd[m][0] = bd[m][1] = bd[m][2] = 3.4e38f;
            bi[m][0] = bi[m][1] = bi[m][2] = 0;
        }
        const uint32_t lcol2 = (uint32_t)((lane & 3) * 2);   // lane's even col within n8 block

        for (int tile = 0; tile < NT2; tile++) {
            const uint32_t ebase = sb + E_S + (uint32_t)((tile & 1) * 16384);
            const uint32_t esb   = sb + ESQ_S + (uint32_t)((tile & 1) * 512);
            #pragma unroll
            for (int chunk = 0; chunk < 4; chunk++) {
                #pragma unroll
                for (int nb = 0; nb < 4; nb++) {
                    float d0[4] = {0,0,0,0}, d1[4] = {0,0,0,0};
                    #pragma unroll
                    for (int s = 0; s < 4; s++) {
                        uint32_t b0, b1;
                        int brow = chunk * 32 + nb * 8 + (lane & 7);
                        ldmx2(b0, b1, ebase + SWZ((uint32_t)(brow * 128 + s * 32) + ((lane & 8) ? 16u : 0u)));
                        mma16816(d0, af[0][s], b0, b1);
                        mma16816(d1, af[1][s], b0, b1);
                    }
                    // screen: ds = es - 2*dot, candidates in accumulators (no smem round-trip)
                    float2 es = lds64f2(esb + (uint32_t)((chunk * 32 + nb * 8) * 4) + lcol2 * 4);
                    int c0 = tile * 128 + chunk * 32 + nb * 8 + (int)lcol2;
                    float v;
                    v = fmaf(d0[0], -2.0f, es.x); INS3(0, v, c0);
                    v = fmaf(d0[1], -2.0f, es.y); INS3(0, v, c0 + 1);
                    v = fmaf(d0[2], -2.0f, es.x); INS3(1, v, c0);
                    v = fmaf(d0[3], -2.0f, es.y); INS3(1, v, c0 + 1);
                    v = fmaf(d1[0], -2.0f, es.x); INS3(2, v, c0);
                    v = fmaf(d1[1], -2.0f, es.y); INS3(2, v, c0 + 1);
                    v = fmaf(d1[2], -2.0f, es.x); INS3(3, v, c0);
                    v = fmaf(d1[3], -2.0f, es.y); INS3(3, v, c0 + 1);
                }
            }
            __syncthreads();                       // all warps done reading slot tile&1
            if (tile + 2 < NT2) { CP_E(tile + 2, tile & 1); CP_COMMIT(); }
            if (tile + 1 < NT2) {
                if (tile + 2 < NT2) CP_WAIT1(); else CP_WAIT0();
                __syncthreads();                   // slot (tile+1)&1 visible
            }
        }
#undef CP_E

        // merge via per-warp buffer: dbuf[12][32], ibuf[12][32]
        {
            uint32_t wdb = sb + MG_S + (uint32_t)(wid * 3072);
            uint32_t wib = wdb + 1536;
            #pragma unroll
            for (int m = 0; m < 4; m++) {
                uint32_t roff = (uint32_t)(((lane >> 2) + 8 * m) * 4);
                #pragma unroll
                for (int e = 0; e < 3; e++) {
                    uint32_t cidx = (uint32_t)(((lane & 3) * 3 + e) * 128);
                    sts1f(wdb + cidx + roff, bd[m][e]);
                    sts1i(wib + cidx + roff, bi[m][e]);
                }
            }
            __syncwarp();
            // exact rescore of 12 candidates (lineage fp32; lexicographic (d, idx))
            float bdx = 3.4e38f; int bix = 0x7fffffff;
            const float* cbh  = cb + (size_t)h * KCB * DLAT;
            const float* esqf = g_esq + h * KCB;
            #pragma unroll 1
            for (int g = 0; g < 12; g++) {
                int c = lds32i(wib + (uint32_t)(g * 128) + (uint32_t)(lane * 4));
                const float4* e4 = (const float4*)(cbh + (size_t)c * DLAT);
                u64 aA = 0ULL, aB = 0ULL;
                #pragma unroll
                for (int q = 0; q < 16; q++) {
                    float4 ev = e4[q];
                    aA = fma2(pk(ev.x, ev.y), rr[2*q],   aA);
                    aB = fma2(pk(ev.z, ev.w), rr[2*q+1], aB);
                }
                float2 va = upk(aA), vb = upk(aB);
                float dot = __fadd_rn(__fadd_rn(va.x, va.y), __fadd_rn(vb.x, vb.y));
                float dv = __fsub_rn(__fadd_rn(rnorm, esqf[c]), __fmul_rn(2.0f, dot));
                if (dv < bdx || (dv == bdx && c < bix)) { bdx = dv; bix = c; }
            }
            bidx[h] = bix;
            // exact residual update (fp32 sub via fma2(e,-1,r))
            const float4* e4 = (const float4*)(cbh + (size_t)bix * DLAT);
            #pragma unroll
            for (int q = 0; q < 16; q++) {
                float4 ev = e4[q];
                rr[2*q]   = fma2(pk(ev.x, ev.y), NEG1, rr[2*q]);
                rr[2*q+1] = fma2(pk(ev.z, ev.w), NEG1, rr[2*q+1]);
            }
        }
    }

    // ============== Phase 3: out = zq @ Wp + bp (lineage) ==============
    u64 zq[32];
    #pragma unroll
    for (int q = 0; q < 32; q++) zq[q] = 0ULL;
    #pragma unroll
    for (int h = 0; h < NCBK; h++) {
        const float4* e4 = (const float4*)(cb + ((size_t)h * KCB + bidx[h]) * DLAT);
        #pragma unroll
        for (int q = 0; q < 16; q++) {
            float4 ev = e4[q];
            zq[2*q]   = add2(zq[2*q],   pk(ev.x, ev.y));
            zq[2*q+1] = add2(zq[2*q+1], pk(ev.z, ev.w));
        }
    }

    float* orow = out + (size_t)tok * INDIM;
    for (int jc = 0; jc < 16; jc++) {
        __syncthreads();
        {   // Wp[:, jc*32..+32) -> E_S as [d][32]
            float4* dst = (float4*)(smem + E_S);
            #pragma unroll
            for (int i = 0; i < 4; i++) {
                int f4 = t + i * THREADS;
                int d = f4 >> 3, jj4 = f4 & 7;
                dst[f4] = *(const float4*)(Wp + (size_t)d * INDIM + jc * 32 + jj4 * 4);
            }
        }
        __syncthreads();
        {
            u64 acc[16];
            const float2* bpp = (const float2*)(bp + jc * 32);
            #pragma unroll
            for (int q = 0; q < 16; q++) { float2 v = bpp[q]; acc[q] = pk(v.x, v.y); }
            #pragma unroll 4
            for (int dp = 0; dp < 32; dp++) {
                float2 zz = upk(zq[dp]);
                u64 z0p = pk(zz.x, zz.x), z1p = pk(zz.y, zz.y);
                uint32_t row0 = sb + E_S + (uint32_t)((2 * dp) * 128);
                #pragma unroll
                for (int q = 0; q < 8; q++) {
                    u64 a, b; lds_2x64(a, b, row0 + q * 16);
                    acc[2*q]   = fma2(a, z0p, acc[2*q]);
                    acc[2*q+1] = fma2(b, z0p, acc[2*q+1]);
                }
                uint32_t row1 = row0 + 128;
                #pragma unroll
                for (int q = 0; q < 8; q++) {
                    u64 a, b; lds_2x64(a, b, row1 + q * 16);
                    acc[2*q]   = fma2(a, z1p, acc[2*q]);
                    acc[2*q+1] = fma2(b, z1p, acc[2*q+1]);
                }
            }
            float4* od = (float4*)(orow + jc * 32);
            #pragma unroll
            for (int q8 = 0; q8 < 8; q8++) {
                float2 a = upk(acc[2*q8]), b = upk(acc[2*q8+1]);
                float4 v; v.x = a.x; v.y = a.y; v.z = b.x; v.w = b.y;
                od[q8] = v;
            }
        }
    }
}

extern "C" void kernel_launch(void* const* d_in, const int* in_sizes, int n_in,
                              void* d_out, int out_size)
{
    const float* z  = (const float*)d_in[0];
    const float* Wq = (const float*)d_in[1];
    const float* bq = (const float*)d_in[2];
    const float* cb = (const float*)d_in[3];
    const float* Wp = (const float*)d_in[4];
    const float* bp = (const float*)d_in[5];
    float* out = (float*)d_out;

    cudaFuncSetAttribute(fused_vq_kernel, cudaFuncAttributeMaxDynamicSharedMemorySize, SMEM_TOT);
    prep_kernel<<<(NCBK * KCB + 127) / 128, 128>>>(cb);
    fused_vq_kernel<<<NBLK, THREADS, SMEM_TOT>>>(z, Wq, bq, cb, Wp, bp, out);
}

// round 14
// speedup vs baseline: 4.7928x; 1.6593x over previous
#include <cuda_runtime.h>
#include <cuda_bf16.h>
#include <cstdint>
#include <cstddef>

#define NTOK   32768
#define INDIM  512
#define DLAT   64
#define KCB    4096
#define NCBK   4
#define TILE_M 128
#define THREADS 128
#define NBLK   (NTOK / TILE_M)   // 256 CTAs
#define NT2    32                // tiles of 128 codewords

typedef unsigned long long u64;

// Scratch (rewritten every launch -> deterministic)
__device__ __align__(16) float    g_esq[NCBK * KCB];
__device__ __align__(16) uint32_t g_ecbb[NCBK * KCB * 32];   // bf16x2 [h][k][dp], 2MB
__device__ __align__(16) uint32_t g_wph[INDIM * 32];         // Wp hi bf16x2 [n][k2], 64KB
__device__ __align__(16) uint32_t g_wpl[INDIM * 32];         // Wp lo bf16x2 [n][k2], 64KB

// ---- packed f32x2 helpers ----
__device__ __forceinline__ u64 fma2(u64 a, u64 b, u64 c) {
    u64 d; asm("fma.rn.f32x2 %0, %1, %2, %3;" : "=l"(d) : "l"(a), "l"(b), "l"(c)); return d;
}
__device__ __forceinline__ u64 add2(u64 a, u64 b) {
    u64 d; asm("add.rn.f32x2 %0, %1, %2;" : "=l"(d) : "l"(a), "l"(b)); return d;
}
__device__ __forceinline__ u64 pk(float x, float y) {
    u64 d; asm("mov.b64 %0, {%1, %2};" : "=l"(d) : "f"(x), "f"(y)); return d;
}
__device__ __forceinline__ float2 upk(u64 v) {
    float2 r; asm("mov.b64 {%0, %1}, %2;" : "=f"(r.x), "=f"(r.y) : "l"(v)); return r;
}
__device__ __forceinline__ void lds_2x64(u64 &a, u64 &b, uint32_t addr) {
    asm volatile("ld.shared.v2.b64 {%0, %1}, [%2];" : "=l"(a), "=l"(b) : "r"(addr));
}
__device__ __forceinline__ float lds32f(uint32_t a) { float v; asm volatile("ld.shared.f32 %0, [%1];" : "=f"(v) : "r"(a)); return v; }
__device__ __forceinline__ float2 lds64f2(uint32_t a) {
    float2 v; asm volatile("ld.shared.v2.f32 {%0,%1}, [%2];" : "=f"(v.x), "=f"(v.y) : "r"(a)); return v;
}
__device__ __forceinline__ void sts128(uint32_t a, uint32_t c0, uint32_t c1, uint32_t c2, uint32_t c3) {
    asm volatile("st.shared.v4.b32 [%0], {%1,%2,%3,%4};" :: "r"(a), "r"(c0), "r"(c1), "r"(c2), "r"(c3));
}
__device__ __forceinline__ void sts1f(uint32_t a, float x) {
    asm volatile("st.shared.f32 [%0], %1;" :: "r"(a), "f"(x));
}
__device__ __forceinline__ void cpa16(uint32_t dst, const void* src) {
    asm volatile("cp.async.cg.shared.global [%0], [%1], 16;" :: "r"(dst), "l"(src));
}
#define CP_COMMIT() asm volatile("cp.async.commit_group;")
#define CP_WAIT1()  asm volatile("cp.async.wait_group 1;")
#define CP_WAIT0()  asm volatile("cp.async.wait_group 0;")
#define SWZ(x) ((uint32_t)(x) ^ ((((uint32_t)(x)) >> 3) & 0x70))

// ---- warp-level tensor core (sm_80+ path) ----
__device__ __forceinline__ void ldmx4(uint32_t* r, uint32_t addr) {
    asm volatile("ldmatrix.sync.aligned.m8n8.x4.shared.b16 {%0,%1,%2,%3}, [%4];"
                 : "=r"(r[0]), "=r"(r[1]), "=r"(r[2]), "=r"(r[3]) : "r"(addr));
}
__device__ __forceinline__ void ldmx2(uint32_t &r0, uint32_t &r1, uint32_t addr) {
    asm volatile("ldmatrix.sync.aligned.m8n8.x2.shared.b16 {%0,%1}, [%2];"
                 : "=r"(r0), "=r"(r1) : "r"(addr));
}
__device__ __forceinline__ void mma16816(float* d, const uint32_t* a, uint32_t b0, uint32_t b1) {
    asm volatile("mma.sync.aligned.m16n8k16.row.col.f32.bf16.bf16.f32 "
                 "{%0,%1,%2,%3}, {%4,%5,%6,%7}, {%8,%9}, {%0,%1,%2,%3};"
                 : "+f"(d[0]), "+f"(d[1]), "+f"(d[2]), "+f"(d[3])
                 : "r"(a[0]), "r"(a[1]), "r"(a[2]), "r"(a[3]), "r"(b0), "r"(b1));
}

// smem layout (bytes)
#define RB_S    0        // phase2 A / phase3 AH: bf16 swizzled [128][128B] = 16KB
#define AL_S    16384    // phase3 AL tile = 16KB
#define E_S     32768    // 2 slots x 16KB (E tiles / Wq staging / Wp B tiles)
#define ESQ_S   65536    // 2 slots x 512B
#define MG_S    66560    // merge: 4 warps x f32[12][32] = 6KB
#define SMEM_TOT 72704   // x2 CTAs = 145KB <= 228KB/SM

// ---- prep: e_sq (fp32, lineage order) + bf16-packed codebook ----
__global__ void prep_kernel(const float* __restrict__ cb) {
    int idx = blockIdx.x * 128 + threadIdx.x;   // h*4096 + k
    if (idx < NCBK * KCB) {
        const float4* p = (const float4*)(cb + (size_t)idx * DLAT);
        float s = 0.0f;
        #pragma unroll
        for (int q = 0; q < 16; q++) {
            float4 v = p[q];
            s = fmaf(v.x, v.x, s); s = fmaf(v.y, v.y, s);
            s = fmaf(v.z, v.z, s); s = fmaf(v.w, v.w, s);
            uint32_t b0, b1;
            asm("cvt.rn.bf16x2.f32 %0, %1, %2;" : "=r"(b0) : "f"(v.y), "f"(v.x));  // hi=y lo=x
            asm("cvt.rn.bf16x2.f32 %0, %1, %2;" : "=r"(b1) : "f"(v.w), "f"(v.z));
            g_ecbb[(size_t)idx * 32 + 2 * q]     = b0;
            g_ecbb[(size_t)idx * 32 + 2 * q + 1] = b1;
        }
        g_esq[idx] = s;
    }
}

// ---- prep: Wp split into bf16 hi/lo, transposed to [n][k] for B fragments ----
__global__ void prep_wp_kernel(const float* __restrict__ Wp) {
    int n = blockIdx.x * 128 + threadIdx.x;    // 4 blocks x 128 = 512
    if (n < INDIM) {
        #pragma unroll 4
        for (int k2 = 0; k2 < 32; k2++) {
            float w0 = Wp[(size_t)(2 * k2)     * INDIM + n];
            float w1 = Wp[(size_t)(2 * k2 + 1) * INDIM + n];
            uint32_t hp;
            asm("cvt.rn.bf16x2.f32 %0, %1, %2;" : "=r"(hp) : "f"(w1), "f"(w0));
            float h0 = __uint_as_float(hp << 16);
            float h1 = __uint_as_float(hp & 0xFFFF0000u);
            float l0 = w0 - h0, l1 = w1 - h1;
            uint32_t lp;
            asm("cvt.rn.bf16x2.f32 %0, %1, %2;" : "=r"(lp) : "f"(l1), "f"(l0));
            g_wph[n * 32 + k2] = hp;
            g_wpl[n * 32 + k2] = lp;
        }
    }
}

// packed-index branchless top-3 insert (bd0<=bd1<=bd2; index lives in low 12 mantissa bits)
#define INS3P(m, pf) do {                                                      \
    float _x = (pf);                                                           \
    float _mn0 = fminf(bd[m][0], _x), _mx0 = fmaxf(bd[m][0], _x);              \
    bd[m][0] = _mn0;                                                           \
    float _mn1 = fminf(bd[m][1], _mx0), _mx1 = fmaxf(bd[m][1], _mx0);          \
    bd[m][1] = _mn1;                                                           \
    bd[m][2] = fminf(bd[m][2], _mx1);                                          \
} while (0)

__global__ void __launch_bounds__(THREADS, 2)
fused_vq_kernel(const float* __restrict__ z,  const float* __restrict__ Wq,
                const float* __restrict__ bq, const float* __restrict__ cb,
                const float* __restrict__ Wp, const float* __restrict__ bp,
                float* __restrict__ out)
{
    extern __shared__ __align__(16) char smem[];
    const uint32_t sb = (uint32_t)__cvta_generic_to_shared(smem);

    const int t = threadIdx.x, wid = t >> 5, lane = t & 31;
    const int wbase = wid * 32;
    const int tok = blockIdx.x * TILE_M + t;      // thread owns token t end-to-end
    const u64 NEG1 = pk(-1.0f, -1.0f);
    const uint32_t MASKHI = 0xFFFFF000u;

    // ============== Phase 1: zl = z @ Wq + bq (lineage fp32; residual -> rr regs) =========
    u64 rr[32];
    {
        const float2* bq2 = (const float2*)bq;
        #pragma unroll
        for (int q = 0; q < 32; q++) { float2 v = bq2[q]; rr[q] = pk(v.x, v.y); }
    }
    const float4* zrow4 = (const float4*)(z + (size_t)tok * INDIM);
    for (int ic = 0; ic < 8; ic++) {
        __syncthreads();
        {   // Wq rows [ic*64,+64) -> E_S as [row][64]
            const float4* src = (const float4*)(Wq + (size_t)ic * 64 * DLAT);
            float4* dst = (float4*)(smem + E_S);
            #pragma unroll
            for (int i = 0; i < 8; i++) dst[t + i * THREADS] = src[t + i * THREADS];
        }
        __syncthreads();
        for (int i4 = 0; i4 < 16; i4++) {
            float4 zz = zrow4[ic * 16 + i4];
            float zs[4] = {zz.x, zz.y, zz.z, zz.w};
            #pragma unroll
            for (int j = 0; j < 4; j++) {
                u64 zd = pk(zs[j], zs[j]);
                uint32_t base = sb + E_S + (uint32_t)((i4 * 4 + j) * 256);
                #pragma unroll
                for (int q = 0; q < 16; q++) {
                    u64 a, b; lds_2x64(a, b, base + q * 16);
                    rr[2*q]   = fma2(a, zd, rr[2*q]);
                    rr[2*q+1] = fma2(b, zd, rr[2*q+1]);
                }
            }
        }
    }

    // ============== Phase 2: bf16 HMMA screen (packed top-3/lane) -> exact rescore ========
    int bidx[NCBK];

    for (int h = 0; h < NCBK; h++) {
        __syncthreads();   // prior h fully done with E/merge; RB free

        // write residual as bf16 into swizzled A tile (own row)
        #pragma unroll
        for (int u = 0; u < 8; u++) {
            uint32_t c[4];
            #pragma unroll
            for (int j = 0; j < 4; j++) {
                float2 v = upk(rr[u * 4 + j]);
                asm("cvt.rn.bf16x2.f32 %0, %1, %2;" : "=r"(c[j]) : "f"(v.y), "f"(v.x));
            }
            sts128(sb + RB_S + SWZ(t * 128 + u * 16), c[0], c[1], c[2], c[3]);
        }
        __syncwarp();      // A rows written by own warp's lanes only

        // rnorm (lineage chain)
        float rnorm;
        {
            u64 rn2 = 0ULL;
            #pragma unroll
            for (int q = 0; q < 32; q++) rn2 = fma2(rr[q], rr[q], rn2);
            float2 rv = upk(rn2);
            rnorm = __fadd_rn(rv.x, rv.y);
        }

        // A fragments: 2 m16 tiles x 4 ksteps, loaded once per codebook
        uint32_t af[2][4][4];
        {
            int arow = wbase + (lane & 15);
            uint32_t kb = (lane & 16) ? 16u : 0u;
            #pragma unroll
            for (int mt = 0; mt < 2; mt++)
                #pragma unroll
                for (int s = 0; s < 4; s++)
                    ldmx4(af[mt][s], sb + RB_S + SWZ((uint32_t)((arow + 16 * mt) * 128 + s * 32) + kb));
        }

        const char* eb  = (const char*)&g_ecbb[(size_t)h * KCB * 32];   // [k][128B]
        const char* esq = (const char*)&g_esq[h * KCB];

#define CP_E(tile, slot) do {                                                          \
        uint32_t _d0 = sb + E_S + (uint32_t)(slot) * 16384;                            \
        const char* _src = eb + (size_t)(tile) * 128 * 128;                            \
        _Pragma("unroll")                                                              \
        for (int i = 0; i < 8; i++) {                                                  \
            int f = t + i * THREADS; int row = f >> 3, u = f & 7;                      \
            cpa16(_d0 + SWZ(row * 128 + u * 16), _src + (size_t)row * 128 + u * 16);   \
        }                                                                              \
        if (t < 32) cpa16(sb + ESQ_S + (uint32_t)(slot) * 512 + t * 16,                \
                          esq + (size_t)(tile) * 512 + t * 16);                        \
    } while (0)

        CP_E(0, 0); CP_COMMIT();
        CP_E(1, 1); CP_COMMIT();
        CP_WAIT1();
        __syncthreads();   // E(0) visible everywhere

        // per-lane packed top-3 for each of 4 owned row-slots
        float bd[4][3];
        #pragma unroll
        for (int m = 0; m < 4; m++) { bd[m][0] = bd[m][1] = bd[m][2] = 3.4e38f; }
        const uint32_t lcol2 = (uint32_t)((lane & 3) * 2);

        for (int tile = 0; tile < NT2; tile++) {
            const uint32_t ebase = sb + E_S + (uint32_t)((tile & 1) * 16384);
            const uint32_t esb   = sb + ESQ_S + (uint32_t)((tile & 1) * 512);
            #pragma unroll
            for (int chunk = 0; chunk < 4; chunk++) {
                #pragma unroll
                for (int nb = 0; nb < 4; nb++) {
                    float d0[4] = {0,0,0,0}, d1[4] = {0,0,0,0};
                    #pragma unroll
                    for (int s = 0; s < 4; s++) {
                        uint32_t b0, b1;
                        int brow = chunk * 32 + nb * 8 + (lane & 7);
                        ldmx2(b0, b1, ebase + SWZ((uint32_t)(brow * 128 + s * 32) + ((lane & 8) ? 16u : 0u)));
                        mma16816(d0, af[0][s], b0, b1);
                        mma16816(d1, af[1][s], b0, b1);
                    }
                    // screen: ds = es - 2*dot; pack candidate idx into low 12 mantissa bits
                    float2 es = lds64f2(esb + (uint32_t)((chunk * 32 + nb * 8) * 4) + lcol2 * 4);
                    uint32_t ci0 = (uint32_t)((tile * 128 + chunk * 32 + nb * 8 + (int)lcol2) & 0xFFF);
                    uint32_t ci1 = ci0 + 1;
                    float v; uint32_t pv;
                    v = fmaf(d0[0], -2.0f, es.x); pv = (__float_as_uint(v) & MASKHI) | ci0; INS3P(0, __uint_as_float(pv));
                    v = fmaf(d0[1], -2.0f, es.y); pv = (__float_as_uint(v) & MASKHI) | ci1; INS3P(0, __uint_as_float(pv));
                    v = fmaf(d0[2], -2.0f, es.x); pv = (__float_as_uint(v) & MASKHI) | ci0; INS3P(1, __uint_as_float(pv));
                    v = fmaf(d0[3], -2.0f, es.y); pv = (__float_as_uint(v) & MASKHI) | ci1; INS3P(1, __uint_as_float(pv));
                    v = fmaf(d1[0], -2.0f, es.x); pv = (__float_as_uint(v) & MASKHI) | ci0; INS3P(2, __uint_as_float(pv));
                    v = fmaf(d1[1], -2.0f, es.y); pv = (__float_as_uint(v) & MASKHI) | ci1; INS3P(2, __uint_as_float(pv));
                    v = fmaf(d1[2], -2.0f, es.x); pv = (__float_as_uint(v) & MASKHI) | ci0; INS3P(3, __uint_as_float(pv));
                    v = fmaf(d1[3], -2.0f, es.y); pv = (__float_as_uint(v) & MASKHI) | ci1; INS3P(3, __uint_as_float(pv));
                }
            }
            __syncthreads();                       // all warps done reading slot tile&1
            if (tile + 2 < NT2) { CP_E(tile + 2, tile & 1); CP_COMMIT(); }
            if (tile + 1 < NT2) {
                if (tile + 2 < NT2) CP_WAIT1(); else CP_WAIT0();
                __syncthreads();                   // slot (tile+1)&1 visible
            }
        }
#undef CP_E

        // merge via per-warp buffer: dbuf[12][32] packed floats (index embedded)
        {
            uint32_t wdb = sb + MG_S + (uint32_t)(wid * 1536);
            #pragma unroll
            for (int m = 0; m < 4; m++) {
                uint32_t roff = (uint32_t)(((lane >> 2) + 8 * m) * 4);
                #pragma unroll
                for (int e = 0; e < 3; e++)
                    sts1f(wdb + (uint32_t)(((lane & 3) * 3 + e) * 128) + roff, bd[m][e]);
            }
            __syncwarp();
            // exact rescore of 12 candidates (lineage fp32; lexicographic (d, idx))
            float bdx = 3.4e38f; int bix = 0x7fffffff;
            const float* cbh  = cb + (size_t)h * KCB * DLAT;
            const float* esqf = g_esq + h * KCB;
            #pragma unroll 1
            for (int g = 0; g < 12; g++) {
                float pf = lds32f(wdb + (uint32_t)(g * 128) + (uint32_t)(lane * 4));
                int c = (int)(__float_as_uint(pf) & 0xFFFu);
                const float4* e4 = (const float4*)(cbh + (size_t)c * DLAT);
                u64 aA = 0ULL, aB = 0ULL;
                #pragma unroll
                for (int q = 0; q < 16; q++) {
                    float4 ev = e4[q];
                    aA = fma2(pk(ev.x, ev.y), rr[2*q],   aA);
                    aB = fma2(pk(ev.z, ev.w), rr[2*q+1], aB);
                }
                float2 va = upk(aA), vb = upk(aB);
                float dot = __fadd_rn(__fadd_rn(va.x, va.y), __fadd_rn(vb.x, vb.y));
                float dv = __fsub_rn(__fadd_rn(rnorm, esqf[c]), __fmul_rn(2.0f, dot));
                if (dv < bdx || (dv == bdx && c < bix)) { bdx = dv; bix = c; }
            }
            bidx[h] = bix;
            // exact residual update (fp32 sub via fma2(e,-1,r))
            const float4* e4 = (const float4*)(cbh + (size_t)bix * DLAT);
            #pragma unroll
            for (int q = 0; q < 16; q++) {
                float4 ev = e4[q];
                rr[2*q]   = fma2(pk(ev.x, ev.y), NEG1, rr[2*q]);
                rr[2*q+1] = fma2(pk(ev.z, ev.w), NEG1, rr[2*q+1]);
            }
        }
    }

    // ============== Phase 3: out = zq @ Wp + bp via split-bf16 HMMA (err ~2^-16) ==========
    // zq rebuild (lineage: ((e1+e2)+e3)+e4 from exact zero), then hi/lo split into smem.
    {
        u64 zq[32];
        #pragma unroll
        for (int q = 0; q < 32; q++) zq[q] = 0ULL;
        #pragma unroll
        for (int h = 0; h < NCBK; h++) {
            const float4* e4 = (const float4*)(cb + ((size_t)h * KCB + bidx[h]) * DLAT);
            #pragma unroll
            for (int q = 0; q < 16; q++) {
                float4 ev = e4[q];
                zq[2*q]   = add2(zq[2*q],   pk(ev.x, ev.y));
                zq[2*q+1] = add2(zq[2*q+1], pk(ev.z, ev.w));
            }
        }
        __syncthreads();   // phase-2 merge reads done; RB/AL free
        #pragma unroll
        for (int u = 0; u < 8; u++) {
            uint32_t ch[4], cl[4];
            #pragma unroll
            for (int j = 0; j < 4; j++) {
                float2 v = upk(zq[u * 4 + j]);
                uint32_t hp;
                asm("cvt.rn.bf16x2.f32 %0, %1, %2;" : "=r"(hp) : "f"(v.y), "f"(v.x));
                float h0 = __uint_as_float(hp << 16);
                float h1 = __uint_as_float(hp & 0xFFFF0000u);
                float l0 = v.x - h0, l1 = v.y - h1;
                uint32_t lp;
                asm("cvt.rn.bf16x2.f32 %0, %1, %2;" : "=r"(lp) : "f"(l1), "f"(l0));
                ch[j] = hp; cl[j] = lp;
            }
            uint32_t so = SWZ(t * 128 + u * 16);
            sts128(sb + RB_S + so, ch[0], ch[1], ch[2], ch[3]);
            sts128(sb + AL_S + so, cl[0], cl[1], cl[2], cl[3]);
        }
        __syncwarp();
    }

    // A fragments (hi and lo), loaded once
    uint32_t ah[2][4][4], al[2][4][4];
    {
        int arow = wbase + (lane & 15);
        uint32_t kb = (lane & 16) ? 16u : 0u;
        #pragma unroll
        for (int mt = 0; mt < 2; mt++)
            #pragma unroll
            for (int s = 0; s < 4; s++) {
                uint32_t so = SWZ((uint32_t)((arow + 16 * mt) * 128 + s * 32) + kb);
                ldmx4(ah[mt][s], sb + RB_S + so);
                ldmx4(al[mt][s], sb + AL_S + so);
            }
    }

    const int orow0 = blockIdx.x * TILE_M;
    for (int chunk = 0; chunk < 4; chunk++) {
        __syncthreads();   // E slots free
        {   // BH chunk -> slot0, BL chunk -> slot1 (128 n-rows x 128B each)
            const char* bh_src = (const char*)g_wph + (size_t)chunk * 128 * 128;
            const char* bl_src = (const char*)g_wpl + (size_t)chunk * 128 * 128;
            #pragma unroll
            for (int i = 0; i < 8; i++) {
                int f = t + i * THREADS; int row = f >> 3, u = f & 7;
                uint32_t so = SWZ(row * 128 + u * 16);
                cpa16(sb + E_S + so,         bh_src + (size_t)row * 128 + u * 16);
                cpa16(sb + E_S + 16384 + so, bl_src + (size_t)row * 128 + u * 16);
            }
            CP_COMMIT(); CP_WAIT0();
        }
        __syncthreads();
        #pragma unroll 1
        for (int nb = 0; nb < 16; nb++) {
            uint32_t bh[4][2], bl[4][2];
            int brow = nb * 8 + (lane & 7);
            uint32_t koff = (lane & 8) ? 16u : 0u;
            #pragma unroll
            for (int s = 0; s < 4; s++) {
                uint32_t so = SWZ((uint32_t)(brow * 128 + s * 32) + koff);
                ldmx2(bh[s][0], bh[s][1], sb + E_S + so);
                ldmx2(bl[s][0], bl[s][1], sb + E_S + 16384 + so);
            }
            float a0[4] = {0,0,0,0}, a1[4] = {0,0,0,0};
            #pragma unroll
            for (int s = 0; s < 4; s++) {
                mma16816(a0, ah[0][s], bh[s][0], bh[s][1]);
                mma16816(a1, ah[1][s], bh[s][0], bh[s][1]);
            }
            #pragma unroll
            for (int s = 0; s < 4; s++) {
                mma16816(a0, ah[0][s], bl[s][0], bl[s][1]);
                mma16816(a1, ah[1][s], bl[s][0], bl[s][1]);
            }
            #pragma unroll
            for (int s = 0; s < 4; s++) {
                mma16816(a0, al[0][s], bh[s][0], bh[s][1]);
                mma16816(a1, al[1][s], bh[s][0], bh[s][1]);
            }
            // + bias, store directly to gmem
            int col0 = chunk * 128 + nb * 8 + (lane & 3) * 2;
            float2 bpv = *(const float2*)(bp + col0);
            int r0 = wbase + (lane >> 2);
            float2 o00 = make_float2(a0[0] + bpv.x, a0[1] + bpv.y);
            float2 o01 = make_float2(a0[2] + bpv.x, a0[3] + bpv.y);
            float2 o10 = make_float2(a1[0] + bpv.x, a1[1] + bpv.y);
            float2 o11 = make_float2(a1[2] + bpv.x, a1[3] + bpv.y);
            *(float2*)(out + (size_t)(orow0 + r0     ) * INDIM + col0) = o00;
            *(float2*)(out + (size_t)(orow0 + r0 +  8) * INDIM + col0) = o01;
            *(float2*)(out + (size_t)(orow0 + r0 + 16) * INDIM + col0) = o10;
            *(float2*)(out + (size_t)(orow0 + r0 + 24) * INDIM + col0) = o11;
        }
    }
}

extern "C" void kernel_launch(void* const* d_in, const int* in_sizes, int n_in,
                              void* d_out, int out_size)
{
    const float* z  = (const float*)d_in[0];
    const float* Wq = (const float*)d_in[1];
    const float* bq = (const float*)d_in[2];
    const float* cb = (const float*)d_in[3];
    const float* Wp = (const float*)d_in[4];
    const float* bp = (const float*)d_in[5];
    float* out = (float*)d_out;

    cudaFuncSetAttribute(fused_vq_kernel, cudaFuncAttributeMaxDynamicSharedMemorySize, SMEM_TOT);
    prep_kernel<<<(NCBK * KCB + 127) / 128, 128>>>(cb);
    prep_wp_kernel<<<4, 128>>>(Wp);
    fused_vq_kernel<<<NBLK, THREADS, SMEM_TOT>>>(z, Wq, bq, cb, Wp, bp, out);
}

// round 17
// speedup vs baseline: 5.6730x; 1.1836x over previous
#include <cuda_runtime.h>
#include <cuda_bf16.h>
#include <cstdint>
#include <cstddef>

#define NTOK   32768
#define INDIM  512
#define DLAT   64
#define KCB    4096
#define NCBK   4
#define TILE_M 128
#define THREADS 128
#define NBLK   (NTOK / TILE_M)   // 256 CTAs
#define NT2    32                // tiles of 128 codewords

typedef unsigned long long u64;

// Scratch (rewritten every launch -> deterministic)
__device__ __align__(16) float    g_esq[NCBK * KCB];
__device__ __align__(16) uint32_t g_ecbb[NCBK * KCB * 32];   // bf16x2 [h][k][dp], 2MB
__device__ __align__(16) uint32_t g_wph[INDIM * 32];         // Wp hi bf16x2 [n][k2], 64KB
__device__ __align__(16) uint32_t g_wpl[INDIM * 32];         // Wp lo bf16x2 [n][k2], 64KB

// ---- packed f32x2 helpers ----
__device__ __forceinline__ u64 fma2(u64 a, u64 b, u64 c) {
    u64 d; asm("fma.rn.f32x2 %0, %1, %2, %3;" : "=l"(d) : "l"(a), "l"(b), "l"(c)); return d;
}
__device__ __forceinline__ u64 add2(u64 a, u64 b) {
    u64 d; asm("add.rn.f32x2 %0, %1, %2;" : "=l"(d) : "l"(a), "l"(b)); return d;
}
__device__ __forceinline__ u64 pk(float x, float y) {
    u64 d; asm("mov.b64 %0, {%1, %2};" : "=l"(d) : "f"(x), "f"(y)); return d;
}
__device__ __forceinline__ float2 upk(u64 v) {
    float2 r; asm("mov.b64 {%0, %1}, %2;" : "=f"(r.x), "=f"(r.y) : "l"(v)); return r;
}
__device__ __forceinline__ void lds_2x64(u64 &a, u64 &b, uint32_t addr) {
    asm volatile("ld.shared.v2.b64 {%0, %1}, [%2];" : "=l"(a), "=l"(b) : "r"(addr));
}
__device__ __forceinline__ float lds32f(uint32_t a) { float v; asm volatile("ld.shared.f32 %0, [%1];" : "=f"(v) : "r"(a)); return v; }
__device__ __forceinline__ float2 lds64f2(uint32_t a) {
    float2 v; asm volatile("ld.shared.v2.f32 {%0,%1}, [%2];" : "=f"(v.x), "=f"(v.y) : "r"(a)); return v;
}
__device__ __forceinline__ void sts128(uint32_t a, uint32_t c0, uint32_t c1, uint32_t c2, uint32_t c3) {
    asm volatile("st.shared.v4.b32 [%0], {%1,%2,%3,%4};" :: "r"(a), "r"(c0), "r"(c1), "r"(c2), "r"(c3));
}
__device__ __forceinline__ void sts1f(uint32_t a, float x) {
    asm volatile("st.shared.f32 [%0], %1;" :: "r"(a), "f"(x));
}
__device__ __forceinline__ void cpa16(uint32_t dst, const void* src) {
    asm volatile("cp.async.cg.shared.global [%0], [%1], 16;" :: "r"(dst), "l"(src));
}
#define CP_COMMIT() asm volatile("cp.async.commit_group;")
#define CP_WAIT1()  asm volatile("cp.async.wait_group 1;")
#define CP_WAIT0()  asm volatile("cp.async.wait_group 0;")
#define SWZ(x) ((uint32_t)(x) ^ ((((uint32_t)(x)) >> 3) & 0x70))

// ---- warp-level tensor core (sm_80+ path) ----
__device__ __forceinline__ void ldmx4(uint32_t* r, uint32_t addr) {
    asm volatile("ldmatrix.sync.aligned.m8n8.x4.shared.b16 {%0,%1,%2,%3}, [%4];"
                 : "=r"(r[0]), "=r"(r[1]), "=r"(r[2]), "=r"(r[3]) : "r"(addr));
}
__device__ __forceinline__ void ldmx2(uint32_t &r0, uint32_t &r1, uint32_t addr) {
    asm volatile("ldmatrix.sync.aligned.m8n8.x2.shared.b16 {%0,%1}, [%2];"
                 : "=r"(r0), "=r"(r1) : "r"(addr));
}
__device__ __forceinline__ void mma16816(float* d, const uint32_t* a, uint32_t b0, uint32_t b1) {
    asm volatile("mma.sync.aligned.m16n8k16.row.col.f32.bf16.bf16.f32 "
                 "{%0,%1,%2,%3}, {%4,%5,%6,%7}, {%8,%9}, {%0,%1,%2,%3};"
                 : "+f"(d[0]), "+f"(d[1]), "+f"(d[2]), "+f"(d[3])
                 : "r"(a[0]), "r"(a[1]), "r"(a[2]), "r"(a[3]), "r"(b0), "r"(b1));
}

// smem layout (bytes)
#define RB_S    0        // phase2 A / phase3 AH: bf16 swizzled [128][128B] = 16KB
#define AL_S    16384    // phase3 AL tile = 16KB
#define E_S     32768    // 2 slots x 16KB (E tiles / Wq staging / Wp B tiles)
#define ESQ_S   65536    // 2 slots x 512B
#define MG_S    66560    // merge: 4 warps x f32[12][32] = 6KB
#define SMEM_TOT 72704   // x2 CTAs = 145KB <= 228KB/SM

// ---- prep: e_sq (fp32, lineage order) + bf16-packed codebook ----
__global__ void prep_kernel(const float* __restrict__ cb) {
    int idx = blockIdx.x * 128 + threadIdx.x;   // h*4096 + k
    if (idx < NCBK * KCB) {
        const float4* p = (const float4*)(cb + (size_t)idx * DLAT);
        float s = 0.0f;
        #pragma unroll
        for (int q = 0; q < 16; q++) {
            float4 v = p[q];
            s = fmaf(v.x, v.x, s); s = fmaf(v.y, v.y, s);
            s = fmaf(v.z, v.z, s); s = fmaf(v.w, v.w, s);
            uint32_t b0, b1;
            asm("cvt.rn.bf16x2.f32 %0, %1, %2;" : "=r"(b0) : "f"(v.y), "f"(v.x));  // hi=y lo=x
            asm("cvt.rn.bf16x2.f32 %0, %1, %2;" : "=r"(b1) : "f"(v.w), "f"(v.z));
            g_ecbb[(size_t)idx * 32 + 2 * q]     = b0;
            g_ecbb[(size_t)idx * 32 + 2 * q + 1] = b1;
        }
        g_esq[idx] = s;
    }
}

// ---- prep: Wp split into bf16 hi/lo, transposed to [n][k] for B fragments ----
__global__ void prep_wp_kernel(const float* __restrict__ Wp) {
    int n = blockIdx.x * 128 + threadIdx.x;    // 4 blocks x 128 = 512
    if (n < INDIM) {
        #pragma unroll 4
        for (int k2 = 0; k2 < 32; k2++) {
            float w0 = Wp[(size_t)(2 * k2)     * INDIM + n];
            float w1 = Wp[(size_t)(2 * k2 + 1) * INDIM + n];
            uint32_t hp;
            asm("cvt.rn.bf16x2.f32 %0, %1, %2;" : "=r"(hp) : "f"(w1), "f"(w0));
            float h0 = __uint_as_float(hp << 16);
            float h1 = __uint_as_float(hp & 0xFFFF0000u);
            float l0 = w0 - h0, l1 = w1 - h1;
            uint32_t lp;
            asm("cvt.rn.bf16x2.f32 %0, %1, %2;" : "=r"(lp) : "f"(l1), "f"(l0));
            g_wph[n * 32 + k2] = hp;
            g_wpl[n * 32 + k2] = lp;
        }
    }
}

// packed-index branchless top-3 insert (bd0<=bd1<=bd2; index lives in low 12 mantissa bits)
#define INS3P(m, pf) do {                                                      \
    float _x = (pf);                                                           \
    float _mn0 = fminf(bd[m][0], _x), _mx0 = fmaxf(bd[m][0], _x);              \
    bd[m][0] = _mn0;                                                           \
    float _mn1 = fminf(bd[m][1], _mx0), _mx1 = fmaxf(bd[m][1], _mx0);          \
    bd[m][1] = _mn1;                                                           \
    bd[m][2] = fminf(bd[m][2], _mx1);                                          \
} while (0)

__global__ void __launch_bounds__(THREADS, 2)
fused_vq_kernel(const float* __restrict__ z,  const float* __restrict__ Wq,
                const float* __restrict__ bq, const float* __restrict__ cb,
                const float* __restrict__ Wp, const float* __restrict__ bp,
                float* __restrict__ out)
{
    extern __shared__ __align__(16) char smem[];
    const uint32_t sb = (uint32_t)__cvta_generic_to_shared(smem);

    const int t = threadIdx.x, wid = t >> 5, lane = t & 31;
    const int wbase = wid * 32;
    const int tok = blockIdx.x * TILE_M + t;      // thread owns token t end-to-end
    const u64 NEG1 = pk(-1.0f, -1.0f);
    const uint32_t MASKHI = 0xFFFFF000u;

    // ============== Phase 1: zl = z @ Wq + bq (lineage fp32; residual -> rr regs) =========
    u64 rr[32];
    {
        const float2* bq2 = (const float2*)bq;
        #pragma unroll
        for (int q = 0; q < 32; q++) { float2 v = bq2[q]; rr[q] = pk(v.x, v.y); }
    }
    const float4* zrow4 = (const float4*)(z + (size_t)tok * INDIM);
    for (int ic = 0; ic < 8; ic++) {
        __syncthreads();
        {   // Wq rows [ic*64,+64) -> E_S as [row][64]
            const float4* src = (const float4*)(Wq + (size_t)ic * 64 * DLAT);
            float4* dst = (float4*)(smem + E_S);
            #pragma unroll
            for (int i = 0; i < 8; i++) dst[t + i * THREADS] = src[t + i * THREADS];
        }
        __syncthreads();
        for (int i4 = 0; i4 < 16; i4++) {
            float4 zz = zrow4[ic * 16 + i4];
            float zs[4] = {zz.x, zz.y, zz.z, zz.w};
            #pragma unroll
            for (int j = 0; j < 4; j++) {
                u64 zd = pk(zs[j], zs[j]);
                uint32_t base = sb + E_S + (uint32_t)((i4 * 4 + j) * 256);
                #pragma unroll
                for (int q = 0; q < 16; q++) {
                    u64 a, b; lds_2x64(a, b, base + q * 16);
                    rr[2*q]   = fma2(a, zd, rr[2*q]);
                    rr[2*q+1] = fma2(b, zd, rr[2*q+1]);
                }
            }
        }
    }

    // ============== Phase 2: bf16 HMMA screen (pair-min + packed top-3) -> exact rescore ==
    int bidx[NCBK];

    for (int h = 0; h < NCBK; h++) {
        __syncthreads();   // prior h fully done with E/merge; RB free

        // write residual as bf16 into swizzled A tile (own row)
        #pragma unroll
        for (int u = 0; u < 8; u++) {
            uint32_t c[4];
            #pragma unroll
            for (int j = 0; j < 4; j++) {
                float2 v = upk(rr[u * 4 + j]);
                asm("cvt.rn.bf16x2.f32 %0, %1, %2;" : "=r"(c[j]) : "f"(v.y), "f"(v.x));
            }
            sts128(sb + RB_S + SWZ(t * 128 + u * 16), c[0], c[1], c[2], c[3]);
        }
        __syncwarp();      // A rows written by own warp's lanes only

        // rnorm (lineage chain)
        float rnorm;
        {
            u64 rn2 = 0ULL;
            #pragma unroll
            for (int q = 0; q < 32; q++) rn2 = fma2(rr[q], rr[q], rn2);
            float2 rv = upk(rn2);
            rnorm = __fadd_rn(rv.x, rv.y);
        }

        // A fragments: 2 m16 tiles x 4 ksteps, loaded once per codebook
        uint32_t af[2][4][4];
        {
            int arow = wbase + (lane & 15);
            uint32_t kb = (lane & 16) ? 16u : 0u;
            #pragma unroll
            for (int mt = 0; mt < 2; mt++)
                #pragma unroll
                for (int s = 0; s < 4; s++)
                    ldmx4(af[mt][s], sb + RB_S + SWZ((uint32_t)((arow + 16 * mt) * 128 + s * 32) + kb));
        }

        const char* eb  = (const char*)&g_ecbb[(size_t)h * KCB * 32];   // [k][128B]
        const char* esq = (const char*)&g_esq[h * KCB];

#define CP_E(tile, slot) do {                                                          \
        uint32_t _d0 = sb + E_S + (uint32_t)(slot) * 16384;                            \
        const char* _src = eb + (size_t)(tile) * 128 * 128;                            \
        _Pragma("unroll")                                                              \
        for (int i = 0; i < 8; i++) {                                                  \
            int f = t + i * THREADS; int row = f >> 3, u = f & 7;                      \
            cpa16(_d0 + SWZ(row * 128 + u * 16), _src + (size_t)row * 128 + u * 16);   \
        }                                                                              \
        if (t < 32) cpa16(sb + ESQ_S + (uint32_t)(slot) * 512 + t * 16,                \
                          esq + (size_t)(tile) * 512 + t * 16);                        \
    } while (0)

        CP_E(0, 0); CP_COMMIT();
        CP_E(1, 1); CP_COMMIT();
        CP_WAIT1();
        __syncthreads();   // E(0) visible everywhere

        // per-lane packed top-3 for each of 4 owned row-slots
        float bd[4][3];
        #pragma unroll
        for (int m = 0; m < 4; m++) { bd[m][0] = bd[m][1] = bd[m][2] = 3.4e38f; }
        const uint32_t lcol2 = (uint32_t)((lane & 3) * 2);
        const uint32_t g16 = (uint32_t)((lane >> 3) * 16);   // ldmx4 lane-group col offset

        for (int tile = 0; tile < NT2; tile++) {
            const uint32_t ebase = sb + E_S + (uint32_t)((tile & 1) * 16384);
            const uint32_t esb   = sb + ESQ_S + (uint32_t)((tile & 1) * 512);
            #pragma unroll
            for (int chunk = 0; chunk < 4; chunk++) {
                #pragma unroll
                for (int nb = 0; nb < 4; nb++) {
                    float d0[4] = {0,0,0,0}, d1[4] = {0,0,0,0};
                    uint32_t bf[8];
                    {
                        int brow = chunk * 32 + nb * 8 + (lane & 7);
                        ldmx4(bf,     ebase + SWZ((uint32_t)(brow * 128)      + g16));
                        ldmx4(bf + 4, ebase + SWZ((uint32_t)(brow * 128 + 64) + g16));
                    }
                    #pragma unroll
                    for (int s = 0; s < 4; s++) {
                        mma16816(d0, af[0][s], bf[2*s], bf[2*s+1]);
                        mma16816(d1, af[1][s], bf[2*s], bf[2*s+1]);
                    }
                    // screen: ds = es - 2*dot; pack idx into low 12 mantissa bits;
                    // pair-min (even/odd col) then single top-3 insert per slot
                    float2 es = lds64f2(esb + (uint32_t)((chunk * 32 + nb * 8) * 4) + lcol2 * 4);
                    uint32_t ci0 = (uint32_t)((tile * 128 + chunk * 32 + nb * 8 + (int)lcol2) & 0xFFF);
                    uint32_t ci1 = ci0 + 1;
                    float va, vb;
                    va = __uint_as_float((__float_as_uint(fmaf(d0[0], -2.0f, es.x)) & MASKHI) | ci0);
                    vb = __uint_as_float((__float_as_uint(fmaf(d0[1], -2.0f, es.y)) & MASKHI) | ci1);
                    INS3P(0, fminf(va, vb));
                    va = __uint_as_float((__float_as_uint(fmaf(d0[2], -2.0f, es.x)) & MASKHI) | ci0);
                    vb = __uint_as_float((__float_as_uint(fmaf(d0[3], -2.0f, es.y)) & MASKHI) | ci1);
                    INS3P(1, fminf(va, vb));
                    va = __uint_as_float((__float_as_uint(fmaf(d1[0], -2.0f, es.x)) & MASKHI) | ci0);
                    vb = __uint_as_float((__float_as_uint(fmaf(d1[1], -2.0f, es.y)) & MASKHI) | ci1);
                    INS3P(2, fminf(va, vb));
                    va = __uint_as_float((__float_as_uint(fmaf(d1[2], -2.0f, es.x)) & MASKHI) | ci0);
                    vb = __uint_as_float((__float_as_uint(fmaf(d1[3], -2.0f, es.y)) & MASKHI) | ci1);
                    INS3P(3, fminf(va, vb));
                }
            }
            __syncthreads();                       // all warps done reading slot tile&1
            if (tile + 2 < NT2) { CP_E(tile + 2, tile & 1); CP_COMMIT(); }
            if (tile + 1 < NT2) {
                if (tile + 2 < NT2) CP_WAIT1(); else CP_WAIT0();
                __syncthreads();                   // slot (tile+1)&1 visible
            }
        }
#undef CP_E

        // merge via per-warp buffer: dbuf[12][32] packed floats (index embedded)
        {
            uint32_t wdb = sb + MG_S + (uint32_t)(wid * 1536);
            #pragma unroll
            for (int m = 0; m < 4; m++) {
                uint32_t roff = (uint32_t)(((lane >> 2) + 8 * m) * 4);
                #pragma unroll
                for (int e = 0; e < 3; e++)
                    sts1f(wdb + (uint32_t)(((lane & 3) * 3 + e) * 128) + roff, bd[m][e]);
            }
            __syncwarp();
            // exact rescore of 12 candidates (lineage fp32; lexicographic (d, idx))
            float bdx = 3.4e38f; int bix = 0x7fffffff;
            const float* cbh  = cb + (size_t)h * KCB * DLAT;
            const float* esqf = g_esq + h * KCB;
            #pragma unroll 1
            for (int g = 0; g < 12; g++) {
                float pf = lds32f(wdb + (uint32_t)(g * 128) + (uint32_t)(lane * 4));
                int c = (int)(__float_as_uint(pf) & 0xFFFu);
                const float4* e4 = (const float4*)(cbh + (size_t)c * DLAT);
                u64 aA = 0ULL, aB = 0ULL;
                #pragma unroll
                for (int q = 0; q < 16; q++) {
                    float4 ev = e4[q];
                    aA = fma2(pk(ev.x, ev.y), rr[2*q],   aA);
                    aB = fma2(pk(ev.z, ev.w), rr[2*q+1], aB);
                }
                float2 va = upk(aA), vb = upk(aB);
                float dot = __fadd_rn(__fadd_rn(va.x, va.y), __fadd_rn(vb.x, vb.y));
                float dv = __fsub_rn(__fadd_rn(rnorm, esqf[c]), __fmul_rn(2.0f, dot));
                if (dv < bdx || (dv == bdx && c < bix)) { bdx = dv; bix = c; }
            }
            bidx[h] = bix;
            // exact residual update (fp32 sub via fma2(e,-1,r))
            const float4* e4 = (const float4*)(cbh + (size_t)bix * DLAT);
            #pragma unroll
            for (int q = 0; q < 16; q++) {
                float4 ev = e4[q];
                rr[2*q]   = fma2(pk(ev.x, ev.y), NEG1, rr[2*q]);
                rr[2*q+1] = fma2(pk(ev.z, ev.w), NEG1, rr[2*q+1]);
            }
        }
    }

    // ============== Phase 3: out = zq @ Wp + bp via split-bf16 HMMA (err ~2^-16) ==========
    // zq rebuild (lineage: ((e1+e2)+e3)+e4 from exact zero), then hi/lo split into smem.
    {
        u64 zq[32];
        #pragma unroll
        for (int q = 0; q < 32; q++) zq[q] = 0ULL;
        #pragma unroll
        for (int h = 0; h < NCBK; h++) {
            const float4* e4 = (const float4*)(cb + ((size_t)h * KCB + bidx[h]) * DLAT);
            #pragma unroll
            for (int q = 0; q < 16; q++) {
                float4 ev = e4[q];
                zq[2*q]   = add2(zq[2*q],   pk(ev.x, ev.y));
                zq[2*q+1] = add2(zq[2*q+1], pk(ev.z, ev.w));
            }
        }
        __syncthreads();   // phase-2 merge reads done; RB/AL free
        #pragma unroll
        for (int u = 0; u < 8; u++) {
            uint32_t ch[4], cl[4];
            #pragma unroll
            for (int j = 0; j < 4; j++) {
                float2 v = upk(zq[u * 4 + j]);
                uint32_t hp;
                asm("cvt.rn.bf16x2.f32 %0, %1, %2;" : "=r"(hp) : "f"(v.y), "f"(v.x));
                float h0 = __uint_as_float(hp << 16);
                float h1 = __uint_as_float(hp & 0xFFFF0000u);
                float l0 = v.x - h0, l1 = v.y - h1;
                uint32_t lp;
                asm("cvt.rn.bf16x2.f32 %0, %1, %2;" : "=r"(lp) : "f"(l1), "f"(l0));
                ch[j] = hp; cl[j] = lp;
            }
            uint32_t so = SWZ(t * 128 + u * 16);
            sts128(sb + RB_S + so, ch[0], ch[1], ch[2], ch[3]);
            sts128(sb + AL_S + so, cl[0], cl[1], cl[2], cl[3]);
        }
        __syncwarp();
    }

    // A fragments (hi and lo), loaded once
    uint32_t ah[2][4][4], al[2][4][4];
    {
        int arow = wbase + (lane & 15);
        uint32_t kb2 = (lane & 16) ? 16u : 0u;
        #pragma unroll
        for (int mt = 0; mt < 2; mt++)
            #pragma unroll
            for (int s = 0; s < 4; s++) {
                uint32_t so = SWZ((uint32_t)((arow + 16 * mt) * 128 + s * 32) + kb2);
                ldmx4(ah[mt][s], sb + RB_S + so);
                ldmx4(al[mt][s], sb + AL_S + so);
            }
    }

    const int orow0 = blockIdx.x * TILE_M;
    for (int chunk = 0; chunk < 4; chunk++) {
        __syncthreads();   // E slots free
        {   // BH chunk -> slot0, BL chunk -> slot1 (128 n-rows x 128B each)
            const char* bh_src = (const char*)g_wph + (size_t)chunk * 128 * 128;
            const char* bl_src = (const char*)g_wpl + (size_t)chunk * 128 * 128;
            #pragma unroll
            for (int i = 0; i < 8; i++) {
                int f = t + i * THREADS; int row = f >> 3, u = f & 7;
                uint32_t so = SWZ(row * 128 + u * 16);
                cpa16(sb + E_S + so,         bh_src + (size_t)row * 128 + u * 16);
                cpa16(sb + E_S + 16384 + so, bl_src + (size_t)row * 128 + u * 16);
            }
            CP_COMMIT(); CP_WAIT0();
        }
        __syncthreads();
        #pragma unroll 1
        for (int nb = 0; nb < 16; nb++) {
            uint32_t bh[4][2], bl[4][2];
            int brow = nb * 8 + (lane & 7);
            uint32_t koff = (lane & 8) ? 16u : 0u;
            #pragma unroll
            for (int s = 0; s < 4; s++) {
                uint32_t so = SWZ((uint32_t)(brow * 128 + s * 32) + koff);
                ldmx2(bh[s][0], bh[s][1], sb + E_S + so);
                ldmx2(bl[s][0], bl[s][1], sb + E_S + 16384 + so);
            }
            float a0[4] = {0,0,0,0}, a1[4] = {0,0,0,0};
            #pragma unroll
            for (int s = 0; s < 4; s++) {
                mma16816(a0, ah[0][s], bh[s][0], bh[s][1]);
                mma16816(a1, ah[1][s], bh[s][0], bh[s][1]);
            }
            #pragma unroll
            for (int s = 0; s < 4; s++) {
                mma16816(a0, ah[0][s], bl[s][0], bl[s][1]);
                mma16816(a1, ah[1][s], bl[s][0], bl[s][1]);
            }
            #pragma unroll
            for (int s = 0; s < 4; s++) {
                mma16816(a0, al[0][s], bh[s][0], bh[s][1]);
                mma16816(a1, al[1][s], bh[s][0], bh[s][1]);
            }
            // + bias, store directly to gmem
            int col0 = chunk * 128 + nb * 8 + (lane & 3) * 2;
            float2 bpv = *(const float2*)(bp + col0);
            int r0 = wbase + (lane >> 2);
            float2 o00 = make_float2(a0[0] + bpv.x, a0[1] + bpv.y);
            float2 o01 = make_float2(a0[2] + bpv.x, a0[3] + bpv.y);
            float2 o10 = make_float2(a1[0] + bpv.x, a1[1] + bpv.y);
            float2 o11 = make_float2(a1[2] + bpv.x, a1[3] + bpv.y);
            *(float2*)(out + (size_t)(orow0 + r0     ) * INDIM + col0) = o00;
            *(float2*)(out + (size_t)(orow0 + r0 +  8) * INDIM + col0) = o01;
            *(float2*)(out + (size_t)(orow0 + r0 + 16) * INDIM + col0) = o10;
            *(float2*)(out + (size_t)(orow0 + r0 + 24) * INDIM + col0) = o11;
        }
    }
}

extern "C" void kernel_launch(void* const* d_in, const int* in_sizes, int n_in,
                              void* d_out, int out_size)
{
    const float* z  = (const float*)d_in[0];
    const float* Wq = (const float*)d_in[1];
    const float* bq = (const float*)d_in[2];
    const float* cb = (const float*)d_in[3];
    const float* Wp = (const float*)d_in[4];
    const float* bp = (const float*)d_in[5];
    float* out = (float*)d_out;

    cudaFuncSetAttribute(fused_vq_kernel, cudaFuncAttributeMaxDynamicSharedMemorySize, SMEM_TOT);
    prep_kernel<<<(NCBK * KCB + 127) / 128, 128>>>(cb);
    prep_wp_kernel<<<4, 128>>>(Wp);
    fused_vq_kernel<<<NBLK, THREADS, SMEM_TOT>>>(z, Wq, bq, cb, Wp, bp, out);
}